// round 2
// baseline (speedup 1.0000x reference)
#include <cuda_runtime.h>

// ---------------- problem constants ----------------
#define BNT   8192      // B*N nodes
#define CCH   256       // channels
#define BB    8
#define NNODE 1024
#define HH    8
#define DKK   32
#define EE    131072
#define C2    512
#define EPSB  1e-5f

// ---------------- device scratch ----------------
__device__ float g_xWn [BNT*CCH];
__device__ float g_xr  [BNT*CCH];
__device__ float g_q   [BNT*CCH];
__device__ float g_k   [BNT*CCH];
__device__ float g_v   [BNT*CCH];
__device__ float g_agg [BNT*CCH];
__device__ float g_h1  [BNT*CCH];
__device__ float g_o   [BNT*CCH];
__device__ float g_h2  [BNT*CCH];
__device__ float g_out0[BNT*CCH];
__device__ float g_hid [BNT*C2];
__device__ float g_out1[BNT*CCH];
__device__ float g_ssum[3][CCH];
__device__ float g_ssq [3][CCH];

// ---------------- zero scratch ----------------
__global__ void zero_kernel() {
    int idx = blockIdx.x * blockDim.x + threadIdx.x;
    if (idx < BNT*CCH/4) ((float4*)g_agg)[idx] = make_float4(0.f,0.f,0.f,0.f);
    if (idx < CCH) {
        #pragma unroll
        for (int s = 0; s < 3; s++) { g_ssum[s][idx] = 0.f; g_ssq[s][idx] = 0.f; }
    }
}

// ---------------- generic SGEMM: C = A[MxK] * B[KxN] (+bias)(+res)(relu) -------
// BM=128, BN=128, BK=8, 256 threads, 8x8 per thread. M%128==0, N%128==0, K%8==0.
#define GBM 128
#define GBN 128
#define GBK 8

__global__ void sgemm_kernel(const float* __restrict__ A, const float* __restrict__ Bm,
                             const float* __restrict__ bias, const float* __restrict__ res,
                             float* __restrict__ Cc, int M, int N, int K, int relu)
{
    __shared__ float As[GBK][GBM];
    __shared__ float Bs[GBK][GBN];

    const int block_row = blockIdx.y;
    const int block_col = blockIdx.x;
    const int tid = threadIdx.x;
    const int tr = tid / 16;         // 0..15
    const int tc = tid % 16;         // 0..15

    const int aRow  = tid >> 1;        // 0..127
    const int aCol4 = (tid & 1) * 4;   // 0 or 4
    const int bRow  = tid >> 5;        // 0..7
    const int bCol4 = (tid & 31) * 4;  // 0..124

    const float* Aptr = A + (long long)(block_row*GBM) * K;
    const float* Bptr = Bm + block_col*GBN;

    float acc[8][8];
    #pragma unroll
    for (int i = 0; i < 8; i++)
        #pragma unroll
        for (int j = 0; j < 8; j++) acc[i][j] = 0.f;

    for (int k0 = 0; k0 < K; k0 += GBK) {
        float4 a4 = *(const float4*)(Aptr + (long long)aRow*K + k0 + aCol4);
        As[aCol4+0][aRow] = a4.x;
        As[aCol4+1][aRow] = a4.y;
        As[aCol4+2][aRow] = a4.z;
        As[aCol4+3][aRow] = a4.w;
        float4 b4 = *(const float4*)(Bptr + (long long)(k0 + bRow)*N + bCol4);
        *(float4*)&Bs[bRow][bCol4] = b4;
        __syncthreads();

        #pragma unroll
        for (int kk = 0; kk < GBK; kk++) {
            float ra[8], rb[8];
            #pragma unroll
            for (int i = 0; i < 8; i++) ra[i] = As[kk][tr*8 + i];
            #pragma unroll
            for (int j = 0; j < 8; j++) rb[j] = Bs[kk][tc*8 + j];
            #pragma unroll
            for (int i = 0; i < 8; i++)
                #pragma unroll
                for (int j = 0; j < 8; j++)
                    acc[i][j] += ra[i] * rb[j];
        }
        __syncthreads();
    }

    const int row0 = block_row*GBM + tr*8;
    const int col0 = block_col*GBN + tc*8;
    #pragma unroll
    for (int i = 0; i < 8; i++) {
        long long r = row0 + i;
        #pragma unroll
        for (int j0 = 0; j0 < 8; j0 += 4) {
            int c = col0 + j0;
            float4 v;
            v.x = acc[i][j0+0]; v.y = acc[i][j0+1];
            v.z = acc[i][j0+2]; v.w = acc[i][j0+3];
            if (bias) {
                v.x += bias[c+0]; v.y += bias[c+1];
                v.z += bias[c+2]; v.w += bias[c+3];
            }
            if (res) {
                float4 rv = *(const float4*)(res + r*N + c);
                v.x += rv.x; v.y += rv.y; v.z += rv.z; v.w += rv.w;
            }
            if (relu) {
                v.x = fmaxf(v.x, 0.f); v.y = fmaxf(v.y, 0.f);
                v.z = fmaxf(v.z, 0.f); v.w = fmaxf(v.w, 0.f);
            }
            *(float4*)(Cc + r*N + c) = v;
        }
    }
}

// ---------------- edge scatter: agg[dst] += xWn[src] ----------------
// edge_index is int32 on device (JAX canonicalizes int64 -> int32 w/o x64).
__global__ void scatter_kernel(const int* __restrict__ ei) {
    int t = blockIdx.x * blockDim.x + threadIdx.x;
    if (t >= EE*64) return;
    int e = t >> 6;
    int j = (t & 63) * 4;
    int src = ei[e];
    int dst = ei[EE + e];
    float4 mv = *(const float4*)(g_xWn + (long long)src*CCH + j);
    float* p = g_agg + (long long)dst*CCH + j;
    atomicAdd(p+0, mv.x);
    atomicAdd(p+1, mv.y);
    atomicAdd(p+2, mv.z);
    atomicAdd(p+3, mv.w);
}

// ---------------- h1pre = x@Wr + agg + x ----------------
__global__ void h1pre_kernel(const float* __restrict__ x) {
    int idx = blockIdx.x * blockDim.x + threadIdx.x;
    if (idx >= BNT*CCH/4) return;
    float4 a = ((const float4*)g_xr)[idx];
    float4 g = ((const float4*)g_agg)[idx];
    float4 xv = ((const float4*)x)[idx];
    a.x += g.x + xv.x; a.y += g.y + xv.y;
    a.z += g.z + xv.z; a.w += g.w + xv.w;
    ((float4*)g_h1)[idx] = a;
}

// ---------------- per-column stats (sum, sumsq) ----------------
__global__ void colstats_kernel(const float* __restrict__ X,
                                float* __restrict__ ssum, float* __restrict__ ssq) {
    int c = threadIdx.x;           // 256 threads = 256 channels
    long long r0 = (long long)blockIdx.x * 64;
    float s = 0.f, q = 0.f;
    #pragma unroll 4
    for (int rr = 0; rr < 64; rr++) {
        float v = X[(r0 + rr)*CCH + c];
        s += v; q += v * v;
    }
    atomicAdd(&ssum[c], s);
    atomicAdd(&ssq[c], q);
}

// ---------------- fused flash attention with sph modulation ----------------
// grid: (N/64, H, B), 256 threads (8 warps x 8 rows)
__global__ void attn_kernel(const float* __restrict__ sph) {
    __shared__ float Qs[64][33];
    __shared__ float Ks[64][33];
    __shared__ float Vs[64][32];
    __shared__ float Ss[64][64];

    const int i0   = blockIdx.x * 64;
    const int h    = blockIdx.y;
    const int b    = blockIdx.z;
    const int tid  = threadIdx.x;
    const int lane = tid & 31;
    const int w    = tid >> 5;

    const long long base_bh = (long long)b*NNODE*CCH + h*DKK;

    for (int idx = tid; idx < 64*DKK; idx += 256) {
        int r = idx >> 5, c = idx & 31;
        Qs[r][c] = g_q[base_bh + (long long)(i0 + r)*CCH + c];
    }

    float m[8], l[8], acc[8];
    #pragma unroll
    for (int r = 0; r < 8; r++) { m[r] = -1e30f; l[r] = 0.f; acc[r] = 0.f; }

    const float rscale = 0.17677669529663688f;  // 1/sqrt(32)

    for (int jt = 0; jt < NNODE; jt += 64) {
        __syncthreads();
        for (int idx = tid; idx < 64*DKK; idx += 256) {
            int r = idx >> 5, c = idx & 31;
            Ks[r][c] = g_k[base_bh + (long long)(jt + r)*CCH + c];
            Vs[r][c] = g_v[base_bh + (long long)(jt + r)*CCH + c];
        }
        const float* sp = sph + ((long long)b*NNODE + i0)*NNODE + jt;
        for (int idx = tid; idx < 64*64; idx += 256) {
            int r = idx >> 6, c = idx & 63;
            Ss[r][c] = sp[(long long)r*NNODE + c];
        }
        __syncthreads();

        #pragma unroll 1
        for (int r = 0; r < 8; r++) {
            const int i = w*8 + r;
            float s0 = 0.f, s1 = 0.f;
            #pragma unroll
            for (int kk = 0; kk < 32; kk++) {
                float qv = Qs[i][kk];
                s0 += qv * Ks[lane][kk];
                s1 += qv * Ks[lane + 32][kk];
            }
            s0 *= rscale * Ss[i][lane];
            s1 *= rscale * Ss[i][lane + 32];

            float mx = fmaxf(s0, s1);
            #pragma unroll
            for (int off = 16; off > 0; off >>= 1)
                mx = fmaxf(mx, __shfl_xor_sync(0xffffffffu, mx, off));
            float mnew = fmaxf(m[r], mx);

            float p0 = __expf(s0 - mnew);
            float p1 = __expf(s1 - mnew);
            float ps = p0 + p1;
            #pragma unroll
            for (int off = 16; off > 0; off >>= 1)
                ps += __shfl_xor_sync(0xffffffffu, ps, off);

            float corr = __expf(m[r] - mnew);
            m[r] = mnew;
            l[r] = l[r]*corr + ps;
            float a = acc[r]*corr;
            #pragma unroll
            for (int jj = 0; jj < 32; jj++) {
                float pj0 = __shfl_sync(0xffffffffu, p0, jj);
                float pj1 = __shfl_sync(0xffffffffu, p1, jj);
                a += pj0 * Vs[jj][lane];
                a += pj1 * Vs[jj + 32][lane];
            }
            acc[r] = a;
        }
    }

    #pragma unroll
    for (int r = 0; r < 8; r++) {
        int i = i0 + w*8 + r;
        g_o[((long long)b*NNODE + i)*CCH + h*DKK + lane] = acc[r] / l[r];
    }
}

// ---------------- out0 = BN1(h1) + BN2(h2) ----------------
__global__ void bn_combine_kernel(const float* __restrict__ ga1, const float* __restrict__ be1,
                                  const float* __restrict__ ga2, const float* __restrict__ be2) {
    int idx = blockIdx.x * blockDim.x + threadIdx.x;
    if (idx >= BNT*CCH/4) return;
    int c0 = (idx << 2) & (CCH - 1);
    float4 a = ((const float4*)g_h1)[idx];
    float4 bb = ((const float4*)g_h2)[idx];
    float av[4] = {a.x, a.y, a.z, a.w};
    float bv[4] = {bb.x, bb.y, bb.z, bb.w};
    float ov[4];
    const float inv_n = 1.f / (float)BNT;
    #pragma unroll
    for (int j = 0; j < 4; j++) {
        int c = c0 + j;
        float m1 = g_ssum[0][c] * inv_n;
        float v1 = g_ssq[0][c] * inv_n - m1*m1;
        float i1 = rsqrtf(v1 + EPSB);
        float m2 = g_ssum[1][c] * inv_n;
        float v2 = g_ssq[1][c] * inv_n - m2*m2;
        float i2 = rsqrtf(v2 + EPSB);
        ov[j] = (av[j]-m1)*i1*ga1[c] + be1[c] + (bv[j]-m2)*i2*ga2[c] + be2[c];
    }
    ((float4*)g_out0)[idx] = make_float4(ov[0], ov[1], ov[2], ov[3]);
}

// ---------------- final BN3 -> output ----------------
__global__ void bn_final_kernel(const float* __restrict__ ga3, const float* __restrict__ be3,
                                float* __restrict__ out) {
    int idx = blockIdx.x * blockDim.x + threadIdx.x;
    if (idx >= BNT*CCH/4) return;
    int c0 = (idx << 2) & (CCH - 1);
    float4 a = ((const float4*)g_out1)[idx];
    float av[4] = {a.x, a.y, a.z, a.w};
    float ov[4];
    const float inv_n = 1.f / (float)BNT;
    #pragma unroll
    for (int j = 0; j < 4; j++) {
        int c = c0 + j;
        float m3 = g_ssum[2][c] * inv_n;
        float v3 = g_ssq[2][c] * inv_n - m3*m3;
        float i3 = rsqrtf(v3 + EPSB);
        ov[j] = (av[j]-m3)*i3*ga3[c] + be3[c];
    }
    ((float4*)out)[idx] = make_float4(ov[0], ov[1], ov[2], ov[3]);
}

// ---------------- launcher ----------------
extern "C" void kernel_launch(void* const* d_in, const int* in_sizes, int n_in,
                              void* d_out, int out_size) {
    const float* x    = (const float*)d_in[0];
    const int*   eidx = (const int*)d_in[1];
    const float* sph  = (const float*)d_in[2];
    const float* Wr   = (const float*)d_in[3];
    const float* Wn   = (const float*)d_in[4];
    const float* Wq   = (const float*)d_in[5];
    const float* bq   = (const float*)d_in[6];
    const float* Wk   = (const float*)d_in[7];
    const float* bk   = (const float*)d_in[8];
    const float* Wv   = (const float*)d_in[9];
    const float* bv   = (const float*)d_in[10];
    const float* Wo   = (const float*)d_in[11];
    const float* bo   = (const float*)d_in[12];
    const float* W1   = (const float*)d_in[13];
    const float* b1   = (const float*)d_in[14];
    const float* W2   = (const float*)d_in[15];
    const float* b2   = (const float*)d_in[16];
    const float* ga1  = (const float*)d_in[17];
    const float* be1  = (const float*)d_in[18];
    const float* ga2  = (const float*)d_in[19];
    const float* be2  = (const float*)d_in[20];
    const float* ga3  = (const float*)d_in[21];
    const float* be3  = (const float*)d_in[22];
    float* out = (float*)d_out;

    float *p_xWn, *p_xr, *p_q, *p_k, *p_v, *p_h1, *p_o, *p_h2, *p_out0, *p_hid, *p_out1;
    float *p_ssum, *p_ssq;
    cudaGetSymbolAddress((void**)&p_xWn,  g_xWn);
    cudaGetSymbolAddress((void**)&p_xr,   g_xr);
    cudaGetSymbolAddress((void**)&p_q,    g_q);
    cudaGetSymbolAddress((void**)&p_k,    g_k);
    cudaGetSymbolAddress((void**)&p_v,    g_v);
    cudaGetSymbolAddress((void**)&p_h1,   g_h1);
    cudaGetSymbolAddress((void**)&p_o,    g_o);
    cudaGetSymbolAddress((void**)&p_h2,   g_h2);
    cudaGetSymbolAddress((void**)&p_out0, g_out0);
    cudaGetSymbolAddress((void**)&p_hid,  g_hid);
    cudaGetSymbolAddress((void**)&p_out1, g_out1);
    cudaGetSymbolAddress((void**)&p_ssum, g_ssum);
    cudaGetSymbolAddress((void**)&p_ssq,  g_ssq);

    const int elem4_blocks = (BNT*CCH/4 + 255) / 256;    // 2048

    zero_kernel<<<elem4_blocks, 256>>>();

    dim3 gC (CCH/GBN,  BNT/GBM);   // (2, 64)
    dim3 gC2(C2/GBN,   BNT/GBM);   // (4, 64)

    // projections
    sgemm_kernel<<<gC, 256>>>(x, Wn, nullptr, nullptr, p_xWn, BNT, CCH, CCH, 0);
    sgemm_kernel<<<gC, 256>>>(x, Wr, nullptr, nullptr, p_xr,  BNT, CCH, CCH, 0);
    sgemm_kernel<<<gC, 256>>>(x, Wq, bq, nullptr, p_q, BNT, CCH, CCH, 0);
    sgemm_kernel<<<gC, 256>>>(x, Wk, bk, nullptr, p_k, BNT, CCH, CCH, 0);
    sgemm_kernel<<<gC, 256>>>(x, Wv, bv, nullptr, p_v, BNT, CCH, CCH, 0);

    // edge aggregation
    scatter_kernel<<<EE*64/256, 256>>>(eidx);

    // branch 1 pre-BN + stats
    h1pre_kernel<<<elem4_blocks, 256>>>(x);
    colstats_kernel<<<BNT/64, 256>>>(p_h1, p_ssum + 0*CCH, p_ssq + 0*CCH);

    // branch 2: attention + output projection (+x residual) + stats
    attn_kernel<<<dim3(NNODE/64, HH, BB), 256>>>(sph);
    sgemm_kernel<<<gC, 256>>>(p_o, Wo, bo, x, p_h2, BNT, CCH, CCH, 0);
    colstats_kernel<<<BNT/64, 256>>>(p_h2, p_ssum + 1*CCH, p_ssq + 1*CCH);

    // combine BN branches
    bn_combine_kernel<<<elem4_blocks, 256>>>(ga1, be1, ga2, be2);

    // MLP
    sgemm_kernel<<<gC2, 256>>>(p_out0, W1, b1, nullptr, p_hid, BNT, C2, CCH, 1);
    sgemm_kernel<<<gC, 256>>>(p_hid, W2, b2, p_out0, p_out1, BNT, CCH, C2, 0);
    colstats_kernel<<<BNT/64, 256>>>(p_out1, p_ssum + 2*CCH, p_ssq + 2*CCH);

    // final BN
    bn_final_kernel<<<elem4_blocks, 256>>>(ga3, be3, out);
}

// round 3
// speedup vs baseline: 1.4303x; 1.4303x over previous
#include <cuda_runtime.h>

// ---------------- problem constants ----------------
#define BNT   8192      // B*N nodes
#define CCH   256       // channels
#define BB    8
#define NNODE 1024
#define HH    8
#define DKK   32
#define EE    131072
#define C2    512
#define EPSB  1e-5f

// ---------------- device scratch ----------------
__device__ float g_xWn [BNT*CCH];
__device__ float g_xr  [BNT*CCH];
__device__ float g_q   [BNT*CCH];
__device__ float g_k   [BNT*CCH];
__device__ float g_v   [BNT*CCH];
__device__ float g_agg [BNT*CCH];
__device__ float g_h1  [BNT*CCH];
__device__ float g_o   [BNT*CCH];
__device__ float g_h2  [BNT*CCH];
__device__ float g_out0[BNT*CCH];
__device__ float g_hid [BNT*C2];
__device__ float g_out1[BNT*CCH];
__device__ float g_ssum[3][CCH];
__device__ float g_ssq [3][CCH];

// ---------------- zero scratch ----------------
__global__ void zero_kernel() {
    int idx = blockIdx.x * blockDim.x + threadIdx.x;
    if (idx < BNT*CCH/4) ((float4*)g_agg)[idx] = make_float4(0.f,0.f,0.f,0.f);
    if (idx < CCH) {
        #pragma unroll
        for (int s = 0; s < 3; s++) { g_ssum[s][idx] = 0.f; g_ssq[s][idx] = 0.f; }
    }
}

// =======================================================================
// GEMM core: 128x128 tile, BK=8, 256 threads, 8x8 per thread
// =======================================================================
#define GBM 128
#define GBN 128
#define GBK 8

__device__ __forceinline__ void gemm_core(
    const float* __restrict__ A, const float* __restrict__ Bm,
    const float* __restrict__ bias, const float* __restrict__ res,
    float* __restrict__ Cc, int N, int K, int block_row, int block_col, int relu,
    float (*As)[GBM], float (*Bs)[GBN])
{
    const int tid = threadIdx.x;
    const int tr = tid / 16;
    const int tc = tid % 16;

    const int aRow  = tid >> 1;
    const int aCol4 = (tid & 1) * 4;
    const int bRow  = tid >> 5;
    const int bCol4 = (tid & 31) * 4;

    const float* Aptr = A + (long long)(block_row*GBM) * K;
    const float* Bptr = Bm + block_col*GBN;

    float acc[8][8];
    #pragma unroll
    for (int i = 0; i < 8; i++)
        #pragma unroll
        for (int j = 0; j < 8; j++) acc[i][j] = 0.f;

    for (int k0 = 0; k0 < K; k0 += GBK) {
        float4 a4 = *(const float4*)(Aptr + (long long)aRow*K + k0 + aCol4);
        As[aCol4+0][aRow] = a4.x;
        As[aCol4+1][aRow] = a4.y;
        As[aCol4+2][aRow] = a4.z;
        As[aCol4+3][aRow] = a4.w;
        float4 b4 = *(const float4*)(Bptr + (long long)(k0 + bRow)*N + bCol4);
        *(float4*)&Bs[bRow][bCol4] = b4;
        __syncthreads();

        #pragma unroll
        for (int kk = 0; kk < GBK; kk++) {
            float ra[8], rb[8];
            #pragma unroll
            for (int i = 0; i < 8; i++) ra[i] = As[kk][tr*8 + i];
            #pragma unroll
            for (int j = 0; j < 8; j++) rb[j] = Bs[kk][tc*8 + j];
            #pragma unroll
            for (int i = 0; i < 8; i++)
                #pragma unroll
                for (int j = 0; j < 8; j++)
                    acc[i][j] += ra[i] * rb[j];
        }
        __syncthreads();
    }

    const int row0 = block_row*GBM + tr*8;
    const int col0 = block_col*GBN + tc*8;
    #pragma unroll
    for (int i = 0; i < 8; i++) {
        long long r = row0 + i;
        #pragma unroll
        for (int j0 = 0; j0 < 8; j0 += 4) {
            int c = col0 + j0;
            float4 v;
            v.x = acc[i][j0+0]; v.y = acc[i][j0+1];
            v.z = acc[i][j0+2]; v.w = acc[i][j0+3];
            if (bias) {
                v.x += bias[c+0]; v.y += bias[c+1];
                v.z += bias[c+2]; v.w += bias[c+3];
            }
            if (res) {
                float4 rv = *(const float4*)(res + r*N + c);
                v.x += rv.x; v.y += rv.y; v.z += rv.z; v.w += rv.w;
            }
            if (relu) {
                v.x = fmaxf(v.x, 0.f); v.y = fmaxf(v.y, 0.f);
                v.z = fmaxf(v.z, 0.f); v.w = fmaxf(v.w, 0.f);
            }
            *(float4*)(Cc + r*N + c) = v;
        }
    }
}

// ---------------- generic SGEMM (Wo, MLP) ----------------
__global__ __launch_bounds__(256, 2)
void sgemm_kernel(const float* __restrict__ A, const float* __restrict__ Bm,
                  const float* __restrict__ bias, const float* __restrict__ res,
                  float* __restrict__ Cc, int N, int K, int relu)
{
    __shared__ float As[GBK][GBM];
    __shared__ float Bs[GBK][GBN];
    gemm_core(A, Bm, bias, res, Cc, N, K, blockIdx.y, blockIdx.x, relu, As, Bs);
}

// ---------------- merged 5-way projection GEMM ----------------
struct P5 {
    const float* B[5];
    const float* bias[5];
    float*       C[5];
};

__global__ __launch_bounds__(256, 2)
void proj_gemm_kernel(const float* __restrict__ A, P5 p)
{
    __shared__ float As[GBK][GBM];
    __shared__ float Bs[GBK][GBN];
    const int bw = blockIdx.x >> 1;       // which weight (0..4)
    const int bc = blockIdx.x & 1;        // which 128-col half
    gemm_core(A, p.B[bw], p.bias[bw], nullptr, p.C[bw],
              CCH, CCH, blockIdx.y, bc, 0, As, Bs);
}

// ---------------- edge scatter: agg[dst] += xWn[src] ----------------
__global__ void scatter_kernel(const int* __restrict__ ei) {
    int t = blockIdx.x * blockDim.x + threadIdx.x;
    if (t >= EE*64) return;
    int e = t >> 6;
    int j = (t & 63) * 4;
    int src = ei[e];
    int dst = ei[EE + e];
    float4 mv = *(const float4*)(g_xWn + (long long)src*CCH + j);
    float* p = g_agg + (long long)dst*CCH + j;
    atomicAdd(p+0, mv.x);
    atomicAdd(p+1, mv.y);
    atomicAdd(p+2, mv.z);
    atomicAdd(p+3, mv.w);
}

// ---------------- h1pre = x@Wr + agg + x ----------------
__global__ void h1pre_kernel(const float* __restrict__ x) {
    int idx = blockIdx.x * blockDim.x + threadIdx.x;
    if (idx >= BNT*CCH/4) return;
    float4 a = ((const float4*)g_xr)[idx];
    float4 g = ((const float4*)g_agg)[idx];
    float4 xv = ((const float4*)x)[idx];
    a.x += g.x + xv.x; a.y += g.y + xv.y;
    a.z += g.z + xv.z; a.w += g.w + xv.w;
    ((float4*)g_h1)[idx] = a;
}

// ---------------- per-column stats: h1 -> slot0, h2 -> slot1 (fused) ---
__global__ void colstats2_kernel() {
    int c = threadIdx.x;
    long long r0 = (long long)blockIdx.x * 64;
    float s1 = 0.f, q1 = 0.f, s2 = 0.f, q2 = 0.f;
    #pragma unroll 4
    for (int rr = 0; rr < 64; rr++) {
        float v1 = g_h1[(r0 + rr)*CCH + c];
        float v2 = g_h2[(r0 + rr)*CCH + c];
        s1 += v1; q1 += v1 * v1;
        s2 += v2; q2 += v2 * v2;
    }
    atomicAdd(&g_ssum[0][c], s1);
    atomicAdd(&g_ssq [0][c], q1);
    atomicAdd(&g_ssum[1][c], s2);
    atomicAdd(&g_ssq [1][c], q2);
}

__global__ void colstats_kernel(const float* __restrict__ X,
                                float* __restrict__ ssum, float* __restrict__ ssq) {
    int c = threadIdx.x;
    long long r0 = (long long)blockIdx.x * 64;
    float s = 0.f, q = 0.f;
    #pragma unroll 4
    for (int rr = 0; rr < 64; rr++) {
        float v = X[(r0 + rr)*CCH + c];
        s += v; q += v * v;
    }
    atomicAdd(&ssum[c], s);
    atomicAdd(&ssq[c], q);
}

// =======================================================================
// Flash attention with sph modulation (GEMM-style, no shuffles in PV)
// grid: (N/64, H, B), 256 threads
// =======================================================================
__global__ __launch_bounds__(256)
void attn_kernel(const float* __restrict__ sph) {
    __shared__ float Qs[64][33];
    __shared__ float Ks[64][33];
    __shared__ float Vs[64][33];
    __shared__ float Ps[64][64];

    const int i0   = blockIdx.x * 64;
    const int h    = blockIdx.y;
    const int b    = blockIdx.z;
    const int tid  = threadIdx.x;
    const int lane = tid & 31;
    const int w    = tid >> 5;

    const int tr = tid >> 4;   // 0..15 -> rows tr*4..tr*4+3
    const int tc = tid & 15;   // cols tc*4..tc*4+3

    const long long base = (long long)b*NNODE*CCH + h*DKK;

    // load Q tile
    for (int idx = tid; idx < 64*DKK; idx += 256) {
        int r = idx >> 5, c = idx & 31;
        Qs[r][c] = g_q[base + (long long)(i0 + r)*CCH + c];
    }

    float m[8], l[8], acc[8];
    #pragma unroll
    for (int r = 0; r < 8; r++) { m[r] = -1e30f; l[r] = 0.f; acc[r] = 0.f; }

    const float rscale = 0.17677669529663688f;  // 1/sqrt(32)
    const float* sp = sph + ((long long)b*NNODE + i0)*NNODE;

    for (int jt = 0; jt < NNODE; jt += 64) {
        __syncthreads();
        for (int idx = tid; idx < 64*DKK; idx += 256) {
            int r = idx >> 5, c = idx & 31;
            Ks[r][c] = g_k[base + (long long)(jt + r)*CCH + c];
            Vs[r][c] = g_v[base + (long long)(jt + r)*CCH + c];
        }
        __syncthreads();

        // ---- S = Q K^T : 4x4 register tile per thread ----
        {
            float a4[4][4];
            #pragma unroll
            for (int u = 0; u < 4; u++)
                #pragma unroll
                for (int vv = 0; vv < 4; vv++) a4[u][vv] = 0.f;

            #pragma unroll
            for (int kk = 0; kk < 32; kk++) {
                float ra[4], rb[4];
                #pragma unroll
                for (int u = 0; u < 4; u++) ra[u] = Qs[tr*4 + u][kk];
                #pragma unroll
                for (int vv = 0; vv < 4; vv++) rb[vv] = Ks[tc*4 + vv][kk];
                #pragma unroll
                for (int u = 0; u < 4; u++)
                    #pragma unroll
                    for (int vv = 0; vv < 4; vv++)
                        a4[u][vv] += ra[u] * rb[vv];
            }
            #pragma unroll
            for (int u = 0; u < 4; u++)
                *(float4*)&Ps[tr*4 + u][tc*4] =
                    make_float4(a4[u][0], a4[u][1], a4[u][2], a4[u][3]);
        }
        __syncthreads();

        // ---- softmax (online) : warp w owns rows w*8..w*8+7 ----
        #pragma unroll 1
        for (int r = 0; r < 8; r++) {
            const int i = w*8 + r;
            const float* spr = sp + (long long)i*NNODE + jt;
            float s0 = Ps[i][lane]      * rscale * spr[lane];
            float s1 = Ps[i][lane + 32] * rscale * spr[lane + 32];

            float mx = fmaxf(s0, s1);
            #pragma unroll
            for (int off = 16; off > 0; off >>= 1)
                mx = fmaxf(mx, __shfl_xor_sync(0xffffffffu, mx, off));
            float mnew = fmaxf(m[r], mx);

            float p0 = __expf(s0 - mnew);
            float p1 = __expf(s1 - mnew);
            float ps = p0 + p1;
            #pragma unroll
            for (int off = 16; off > 0; off >>= 1)
                ps += __shfl_xor_sync(0xffffffffu, ps, off);

            float corr = __expf(m[r] - mnew);
            m[r] = mnew;
            l[r] = l[r]*corr + ps;
            acc[r] *= corr;

            Ps[i][lane]      = p0;
            Ps[i][lane + 32] = p1;
        }
        __syncthreads();

        // ---- O += P V : warp w rows, col d = lane ----
        #pragma unroll
        for (int jj = 0; jj < 64; jj += 4) {
            float v0 = Vs[jj+0][lane];
            float v1 = Vs[jj+1][lane];
            float v2 = Vs[jj+2][lane];
            float v3 = Vs[jj+3][lane];
            #pragma unroll
            for (int r = 0; r < 8; r++) {
                float4 pp = *(const float4*)&Ps[w*8 + r][jj];
                acc[r] += pp.x*v0 + pp.y*v1 + pp.z*v2 + pp.w*v3;
            }
        }
    }

    #pragma unroll
    for (int r = 0; r < 8; r++) {
        int i = i0 + w*8 + r;
        g_o[((long long)b*NNODE + i)*CCH + h*DKK + lane] = acc[r] / l[r];
    }
}

// ---------------- out0 = BN1(h1) + BN2(h2) ----------------
__global__ void bn_combine_kernel(const float* __restrict__ ga1, const float* __restrict__ be1,
                                  const float* __restrict__ ga2, const float* __restrict__ be2) {
    int idx = blockIdx.x * blockDim.x + threadIdx.x;
    if (idx >= BNT*CCH/4) return;
    int c0 = (idx << 2) & (CCH - 1);
    float4 a = ((const float4*)g_h1)[idx];
    float4 bb = ((const float4*)g_h2)[idx];
    float av[4] = {a.x, a.y, a.z, a.w};
    float bv[4] = {bb.x, bb.y, bb.z, bb.w};
    float ov[4];
    const float inv_n = 1.f / (float)BNT;
    #pragma unroll
    for (int j = 0; j < 4; j++) {
        int c = c0 + j;
        float m1 = g_ssum[0][c] * inv_n;
        float v1 = g_ssq[0][c] * inv_n - m1*m1;
        float i1 = rsqrtf(v1 + EPSB);
        float m2 = g_ssum[1][c] * inv_n;
        float v2 = g_ssq[1][c] * inv_n - m2*m2;
        float i2 = rsqrtf(v2 + EPSB);
        ov[j] = (av[j]-m1)*i1*ga1[c] + be1[c] + (bv[j]-m2)*i2*ga2[c] + be2[c];
    }
    ((float4*)g_out0)[idx] = make_float4(ov[0], ov[1], ov[2], ov[3]);
}

// ---------------- final BN3 -> output ----------------
__global__ void bn_final_kernel(const float* __restrict__ ga3, const float* __restrict__ be3,
                                float* __restrict__ out) {
    int idx = blockIdx.x * blockDim.x + threadIdx.x;
    if (idx >= BNT*CCH/4) return;
    int c0 = (idx << 2) & (CCH - 1);
    float4 a = ((const float4*)g_out1)[idx];
    float av[4] = {a.x, a.y, a.z, a.w};
    float ov[4];
    const float inv_n = 1.f / (float)BNT;
    #pragma unroll
    for (int j = 0; j < 4; j++) {
        int c = c0 + j;
        float m3 = g_ssum[2][c] * inv_n;
        float v3 = g_ssq[2][c] * inv_n - m3*m3;
        float i3 = rsqrtf(v3 + EPSB);
        ov[j] = (av[j]-m3)*i3*ga3[c] + be3[c];
    }
    ((float4*)out)[idx] = make_float4(ov[0], ov[1], ov[2], ov[3]);
}

// ---------------- launcher ----------------
extern "C" void kernel_launch(void* const* d_in, const int* in_sizes, int n_in,
                              void* d_out, int out_size) {
    const float* x    = (const float*)d_in[0];
    const int*   eidx = (const int*)d_in[1];
    const float* sph  = (const float*)d_in[2];
    const float* Wr   = (const float*)d_in[3];
    const float* Wn   = (const float*)d_in[4];
    const float* Wq   = (const float*)d_in[5];
    const float* bq   = (const float*)d_in[6];
    const float* Wk   = (const float*)d_in[7];
    const float* bk   = (const float*)d_in[8];
    const float* Wv   = (const float*)d_in[9];
    const float* bv   = (const float*)d_in[10];
    const float* Wo   = (const float*)d_in[11];
    const float* bo   = (const float*)d_in[12];
    const float* W1   = (const float*)d_in[13];
    const float* b1   = (const float*)d_in[14];
    const float* W2   = (const float*)d_in[15];
    const float* b2   = (const float*)d_in[16];
    const float* ga1  = (const float*)d_in[17];
    const float* be1  = (const float*)d_in[18];
    const float* ga2  = (const float*)d_in[19];
    const float* be2  = (const float*)d_in[20];
    const float* ga3  = (const float*)d_in[21];
    const float* be3  = (const float*)d_in[22];
    float* out = (float*)d_out;

    float *p_xWn, *p_xr, *p_q, *p_k, *p_v, *p_o, *p_h2, *p_out0, *p_hid, *p_out1;
    float *p_ssum, *p_ssq;
    cudaGetSymbolAddress((void**)&p_xWn,  g_xWn);
    cudaGetSymbolAddress((void**)&p_xr,   g_xr);
    cudaGetSymbolAddress((void**)&p_q,    g_q);
    cudaGetSymbolAddress((void**)&p_k,    g_k);
    cudaGetSymbolAddress((void**)&p_v,    g_v);
    cudaGetSymbolAddress((void**)&p_o,    g_o);
    cudaGetSymbolAddress((void**)&p_h2,   g_h2);
    cudaGetSymbolAddress((void**)&p_out0, g_out0);
    cudaGetSymbolAddress((void**)&p_hid,  g_hid);
    cudaGetSymbolAddress((void**)&p_out1, g_out1);
    cudaGetSymbolAddress((void**)&p_ssum, g_ssum);
    cudaGetSymbolAddress((void**)&p_ssq,  g_ssq);

    const int elem4_blocks = (BNT*CCH/4 + 255) / 256;    // 2048

    zero_kernel<<<elem4_blocks, 256>>>();

    // merged projections: xWn, xr, q, k, v in one launch
    P5 p5;
    p5.B[0] = Wn; p5.B[1] = Wr; p5.B[2] = Wq; p5.B[3] = Wk; p5.B[4] = Wv;
    p5.bias[0] = nullptr; p5.bias[1] = nullptr;
    p5.bias[2] = bq; p5.bias[3] = bk; p5.bias[4] = bv;
    p5.C[0] = p_xWn; p5.C[1] = p_xr; p5.C[2] = p_q; p5.C[3] = p_k; p5.C[4] = p_v;
    proj_gemm_kernel<<<dim3(10, BNT/GBM), 256>>>(x, p5);

    // edge aggregation
    scatter_kernel<<<EE*64/256, 256>>>(eidx);

    // branch 1 pre-BN
    h1pre_kernel<<<elem4_blocks, 256>>>(x);

    // branch 2: attention + output projection (+x residual)
    attn_kernel<<<dim3(NNODE/64, HH, BB), 256>>>(sph);
    sgemm_kernel<<<dim3(CCH/GBN, BNT/GBM), 256>>>(p_o, Wo, bo, x, p_h2, CCH, CCH, 0);

    // fused stats for both branches
    colstats2_kernel<<<BNT/64, 256>>>();

    // combine BN branches
    bn_combine_kernel<<<elem4_blocks, 256>>>(ga1, be1, ga2, be2);

    // MLP
    sgemm_kernel<<<dim3(C2/GBN, BNT/GBM), 256>>>(p_out0, W1, b1, nullptr, p_hid, C2, CCH, 1);
    sgemm_kernel<<<dim3(CCH/GBN, BNT/GBM), 256>>>(p_hid, W2, b2, p_out0, p_out1, CCH, C2, 0);
    colstats_kernel<<<BNT/64, 256>>>(p_out1, p_ssum + 2*CCH, p_ssq + 2*CCH);

    // final BN
    bn_final_kernel<<<elem4_blocks, 256>>>(ga3, be3, out);
}

// round 4
// speedup vs baseline: 1.8747x; 1.3107x over previous
#include <cuda_runtime.h>

// ---------------- problem constants ----------------
#define BNT   8192      // B*N nodes
#define CCH   256       // channels
#define BB    8
#define NNODE 1024
#define HH    8
#define DKK   32
#define EE    131072
#define C2    512
#define EPSB  1e-5f

// ---------------- device scratch ----------------
__device__ float g_xWn [BNT*CCH];
__device__ float g_xr  [BNT*CCH];
__device__ float g_q   [BNT*CCH];
__device__ float g_k   [BNT*CCH];
__device__ float g_v   [BNT*CCH];
__device__ float g_agg [BNT*CCH];
__device__ float g_h1  [BNT*CCH];
__device__ float g_o   [BNT*CCH];
__device__ float g_h2  [BNT*CCH];
__device__ float g_out0[BNT*CCH];
__device__ float g_hid [BNT*C2];
__device__ float g_out1[BNT*CCH];
__device__ float g_ssum[3][CCH];
__device__ float g_ssq [3][CCH];

// ---------------- zero scratch ----------------
__global__ void zero_kernel() {
    int idx = blockIdx.x * blockDim.x + threadIdx.x;
    if (idx < BNT*CCH/4) ((float4*)g_agg)[idx] = make_float4(0.f,0.f,0.f,0.f);
    if (idx < CCH) {
        #pragma unroll
        for (int s = 0; s < 3; s++) { g_ssum[s][idx] = 0.f; g_ssq[s][idx] = 0.f; }
    }
}

// =======================================================================
// GEMM core: 128x64 tile, BK=16, 256 threads, 8x4 per thread
// =======================================================================
#define GBM 128
#define GBN 64
#define GBK 16
#define APAD 132
#define BPAD 68

__device__ __forceinline__ void gemm_core(
    const float* __restrict__ A, const float* __restrict__ Bm,
    const float* __restrict__ bias, const float* __restrict__ res,
    float* __restrict__ Cc, int N, int K, int block_row, int block_col, int relu,
    float (*As)[APAD], float (*Bs)[BPAD])
{
    const int tid = threadIdx.x;
    const int tr4 = (tid >> 4) * 8;   // output rows tr4..tr4+7
    const int tc4 = (tid & 15) * 4;   // output cols tc4..tc4+3

    const int aRow = tid >> 1;          // 0..127
    const int aK   = (tid & 1) * 8;     // 0 or 8
    const int bRow = tid >> 4;          // 0..15
    const int bCol = (tid & 15) * 4;    // 0..60

    const float* Aptr = A + (long long)(block_row*GBM) * K;
    const float* Bptr = Bm + block_col*GBN;

    float acc[8][4];
    #pragma unroll
    for (int i = 0; i < 8; i++)
        #pragma unroll
        for (int j = 0; j < 4; j++) acc[i][j] = 0.f;

    for (int k0 = 0; k0 < K; k0 += GBK) {
        // A tile: 128x16, transposed store As[k][row]
        float4 a0 = *(const float4*)(Aptr + (long long)aRow*K + k0 + aK);
        float4 a1 = *(const float4*)(Aptr + (long long)aRow*K + k0 + aK + 4);
        As[aK+0][aRow] = a0.x; As[aK+1][aRow] = a0.y;
        As[aK+2][aRow] = a0.z; As[aK+3][aRow] = a0.w;
        As[aK+4][aRow] = a1.x; As[aK+5][aRow] = a1.y;
        As[aK+6][aRow] = a1.z; As[aK+7][aRow] = a1.w;
        // B tile: 16x64
        *(float4*)&Bs[bRow][bCol] = *(const float4*)(Bptr + (long long)(k0 + bRow)*N + bCol);
        __syncthreads();

        #pragma unroll
        for (int kk = 0; kk < GBK; kk++) {
            float4 ra0 = *(const float4*)&As[kk][tr4];
            float4 ra1 = *(const float4*)&As[kk][tr4 + 4];
            float4 rb  = *(const float4*)&Bs[kk][tc4];
            float ra[8] = {ra0.x, ra0.y, ra0.z, ra0.w, ra1.x, ra1.y, ra1.z, ra1.w};
            float rbv[4] = {rb.x, rb.y, rb.z, rb.w};
            #pragma unroll
            for (int i = 0; i < 8; i++)
                #pragma unroll
                for (int j = 0; j < 4; j++)
                    acc[i][j] += ra[i] * rbv[j];
        }
        __syncthreads();
    }

    const int row0 = block_row*GBM + tr4;
    const int col0 = block_col*GBN + tc4;
    float4 bv = bias ? *(const float4*)(bias + col0) : make_float4(0.f,0.f,0.f,0.f);
    #pragma unroll
    for (int i = 0; i < 8; i++) {
        long long r = row0 + i;
        float4 v;
        v.x = acc[i][0] + bv.x; v.y = acc[i][1] + bv.y;
        v.z = acc[i][2] + bv.z; v.w = acc[i][3] + bv.w;
        if (res) {
            float4 rv = *(const float4*)(res + r*N + col0);
            v.x += rv.x; v.y += rv.y; v.z += rv.z; v.w += rv.w;
        }
        if (relu) {
            v.x = fmaxf(v.x, 0.f); v.y = fmaxf(v.y, 0.f);
            v.z = fmaxf(v.z, 0.f); v.w = fmaxf(v.w, 0.f);
        }
        *(float4*)(Cc + r*N + col0) = v;
    }
}

// ---------------- generic SGEMM (Wo, MLP) ----------------
__global__ __launch_bounds__(256, 3)
void sgemm_kernel(const float* __restrict__ A, const float* __restrict__ Bm,
                  const float* __restrict__ bias, const float* __restrict__ res,
                  float* __restrict__ Cc, int N, int K, int relu)
{
    __shared__ float As[GBK][APAD];
    __shared__ float Bs[GBK][BPAD];
    gemm_core(A, Bm, bias, res, Cc, N, K, blockIdx.y, blockIdx.x, relu, As, Bs);
}

// ---------------- merged 5-way projection GEMM ----------------
struct P5 {
    const float* B[5];
    const float* bias[5];
    float*       C[5];
};

__global__ __launch_bounds__(256, 3)
void proj_gemm_kernel(const float* __restrict__ A, P5 p)
{
    __shared__ float As[GBK][APAD];
    __shared__ float Bs[GBK][BPAD];
    const int bw = blockIdx.x >> 2;       // which weight (0..4)
    const int bc = blockIdx.x & 3;        // which 64-col quarter
    gemm_core(A, p.B[bw], p.bias[bw], nullptr, p.C[bw],
              CCH, CCH, blockIdx.y, bc, 0, As, Bs);
}

// ---------------- edge scatter: agg[dst] += xWn[src] ----------------
__global__ void scatter_kernel(const int* __restrict__ ei) {
    int t = blockIdx.x * blockDim.x + threadIdx.x;
    if (t >= EE*64) return;
    int e = t >> 6;
    int j = (t & 63) * 4;
    int src = ei[e];
    int dst = ei[EE + e];
    float4 mv = *(const float4*)(g_xWn + (long long)src*CCH + j);
    float* p = g_agg + (long long)dst*CCH + j;
    atomicAdd(p+0, mv.x);
    atomicAdd(p+1, mv.y);
    atomicAdd(p+2, mv.z);
    atomicAdd(p+3, mv.w);
}

// ---------------- h1pre = x@Wr + agg + x ----------------
__global__ void h1pre_kernel(const float* __restrict__ x) {
    int idx = blockIdx.x * blockDim.x + threadIdx.x;
    if (idx >= BNT*CCH/4) return;
    float4 a = ((const float4*)g_xr)[idx];
    float4 g = ((const float4*)g_agg)[idx];
    float4 xv = ((const float4*)x)[idx];
    a.x += g.x + xv.x; a.y += g.y + xv.y;
    a.z += g.z + xv.z; a.w += g.w + xv.w;
    ((float4*)g_h1)[idx] = a;
}

// ---------------- per-column stats: h1 -> slot0, h2 -> slot1 (fused) ---
__global__ void colstats2_kernel() {
    int c = threadIdx.x;
    long long r0 = (long long)blockIdx.x * 64;
    float s1 = 0.f, q1 = 0.f, s2 = 0.f, q2 = 0.f;
    #pragma unroll 4
    for (int rr = 0; rr < 64; rr++) {
        float v1 = g_h1[(r0 + rr)*CCH + c];
        float v2 = g_h2[(r0 + rr)*CCH + c];
        s1 += v1; q1 += v1 * v1;
        s2 += v2; q2 += v2 * v2;
    }
    atomicAdd(&g_ssum[0][c], s1);
    atomicAdd(&g_ssq [0][c], q1);
    atomicAdd(&g_ssum[1][c], s2);
    atomicAdd(&g_ssq [1][c], q2);
}

__global__ void colstats_kernel(const float* __restrict__ X,
                                float* __restrict__ ssum, float* __restrict__ ssq) {
    int c = threadIdx.x;
    long long r0 = (long long)blockIdx.x * 64;
    float s = 0.f, q = 0.f;
    #pragma unroll 4
    for (int rr = 0; rr < 64; rr++) {
        float v = X[(r0 + rr)*CCH + c];
        s += v; q += v * v;
    }
    atomicAdd(&ssum[c], s);
    atomicAdd(&ssq[c], q);
}

// =======================================================================
// Attention with sph modulation. No max subtraction (scores bounded),
// transposed smem layouts, exp fused into QK epilogue.
// grid: (N/64, H, B), 256 threads
// =======================================================================
__global__ __launch_bounds__(256, 2)
void attn_kernel(const float* __restrict__ sph) {
    __shared__ float Qt[DKK][68];   // [k][row]
    __shared__ float Kt[DKK][68];   // [k][col j]
    __shared__ float Vt[DKK][76];   // [d][col j]
    __shared__ float Ps[64][64];    // [row][j]
    __shared__ float lsum[64];

    const int i0   = blockIdx.x * 64;
    const int h    = blockIdx.y;
    const int b    = blockIdx.z;
    const int tid  = threadIdx.x;
    const int lane = tid & 31;
    const int w    = tid >> 5;

    const int tr4 = (tid >> 4) * 4;   // rows tr4..tr4+3 (QK phase)
    const int tc4 = (tid & 15) * 4;   // cols tc4..tc4+3 (QK phase)

    const long long base = (long long)b*NNODE*CCH + h*DKK;
    const float rscale = 0.17677669529663688f;  // 1/sqrt(32)

    // load Q tile transposed
    for (int idx = tid; idx < 64*DKK; idx += 256) {
        int r = idx >> 5, c = idx & 31;
        Qt[c][r] = g_q[base + (long long)(i0 + r)*CCH + c];
    }

    float acc[8];
    float rs[4];
    #pragma unroll
    for (int r = 0; r < 8; r++) acc[r] = 0.f;
    #pragma unroll
    for (int u = 0; u < 4; u++) rs[u] = 0.f;

    for (int jt = 0; jt < NNODE; jt += 64) {
        __syncthreads();
        for (int idx = tid; idx < 64*DKK; idx += 256) {
            int r = idx >> 5, c = idx & 31;
            Kt[c][r] = g_k[base + (long long)(jt + r)*CCH + c];
            Vt[c][r] = g_v[base + (long long)(jt + r)*CCH + c];
        }
        __syncthreads();

        // ---- S = Q K^T : 4x4 register tile ----
        float a4[4][4];
        #pragma unroll
        for (int u = 0; u < 4; u++)
            #pragma unroll
            for (int vv = 0; vv < 4; vv++) a4[u][vv] = 0.f;

        #pragma unroll
        for (int kk = 0; kk < DKK; kk++) {
            float4 qa = *(const float4*)&Qt[kk][tr4];
            float4 kb = *(const float4*)&Kt[kk][tc4];
            float ra[4] = {qa.x, qa.y, qa.z, qa.w};
            float rb[4] = {kb.x, kb.y, kb.z, kb.w};
            #pragma unroll
            for (int u = 0; u < 4; u++)
                #pragma unroll
                for (int vv = 0; vv < 4; vv++)
                    a4[u][vv] += ra[u] * rb[vv];
        }

        // ---- modulate by sph, exp, accumulate row-sum partials ----
        #pragma unroll
        for (int u = 0; u < 4; u++) {
            float4 s4 = *(const float4*)(sph +
                ((long long)b*NNODE + i0 + tr4 + u)*NNODE + jt + tc4);
            float p0 = __expf(a4[u][0] * rscale * s4.x);
            float p1 = __expf(a4[u][1] * rscale * s4.y);
            float p2 = __expf(a4[u][2] * rscale * s4.z);
            float p3 = __expf(a4[u][3] * rscale * s4.w);
            rs[u] += (p0 + p1) + (p2 + p3);
            *(float4*)&Ps[tr4 + u][tc4] = make_float4(p0, p1, p2, p3);
        }
        __syncthreads();

        // ---- O += P V : warp w rows w*8..w*8+7, col d = lane ----
        #pragma unroll
        for (int jj = 0; jj < 64; jj += 4) {
            float4 v4 = *(const float4*)&Vt[lane][jj];
            #pragma unroll
            for (int r = 0; r < 8; r++) {
                float4 p4 = *(const float4*)&Ps[w*8 + r][jj];
                acc[r] += p4.x*v4.x + p4.y*v4.y + p4.z*v4.z + p4.w*v4.w;
            }
        }
    }

    // reduce row sums across the 16 threads sharing each row group
    #pragma unroll
    for (int u = 0; u < 4; u++) {
        #pragma unroll
        for (int off = 1; off < 16; off <<= 1)
            rs[u] += __shfl_xor_sync(0xffffffffu, rs[u], off);
    }
    if ((tid & 15) == 0) {
        #pragma unroll
        for (int u = 0; u < 4; u++) lsum[tr4 + u] = rs[u];
    }
    __syncthreads();

    #pragma unroll
    for (int r = 0; r < 8; r++) {
        int i = i0 + w*8 + r;
        g_o[((long long)b*NNODE + i)*CCH + h*DKK + lane] = acc[r] / lsum[w*8 + r];
    }
}

// ---------------- out0 = BN1(h1) + BN2(h2) ----------------
__global__ void bn_combine_kernel(const float* __restrict__ ga1, const float* __restrict__ be1,
                                  const float* __restrict__ ga2, const float* __restrict__ be2) {
    int idx = blockIdx.x * blockDim.x + threadIdx.x;
    if (idx >= BNT*CCH/4) return;
    int c0 = (idx << 2) & (CCH - 1);
    float4 a = ((const float4*)g_h1)[idx];
    float4 bb = ((const float4*)g_h2)[idx];
    float av[4] = {a.x, a.y, a.z, a.w};
    float bv[4] = {bb.x, bb.y, bb.z, bb.w};
    float ov[4];
    const float inv_n = 1.f / (float)BNT;
    #pragma unroll
    for (int j = 0; j < 4; j++) {
        int c = c0 + j;
        float m1 = g_ssum[0][c] * inv_n;
        float v1 = g_ssq[0][c] * inv_n - m1*m1;
        float i1 = rsqrtf(v1 + EPSB);
        float m2 = g_ssum[1][c] * inv_n;
        float v2 = g_ssq[1][c] * inv_n - m2*m2;
        float i2 = rsqrtf(v2 + EPSB);
        ov[j] = (av[j]-m1)*i1*ga1[c] + be1[c] + (bv[j]-m2)*i2*ga2[c] + be2[c];
    }
    ((float4*)g_out0)[idx] = make_float4(ov[0], ov[1], ov[2], ov[3]);
}

// ---------------- final BN3 -> output ----------------
__global__ void bn_final_kernel(const float* __restrict__ ga3, const float* __restrict__ be3,
                                float* __restrict__ out) {
    int idx = blockIdx.x * blockDim.x + threadIdx.x;
    if (idx >= BNT*CCH/4) return;
    int c0 = (idx << 2) & (CCH - 1);
    float4 a = ((const float4*)g_out1)[idx];
    float av[4] = {a.x, a.y, a.z, a.w};
    float ov[4];
    const float inv_n = 1.f / (float)BNT;
    #pragma unroll
    for (int j = 0; j < 4; j++) {
        int c = c0 + j;
        float m3 = g_ssum[2][c] * inv_n;
        float v3 = g_ssq[2][c] * inv_n - m3*m3;
        float i3 = rsqrtf(v3 + EPSB);
        ov[j] = (av[j]-m3)*i3*ga3[c] + be3[c];
    }
    ((float4*)out)[idx] = make_float4(ov[0], ov[1], ov[2], ov[3]);
}

// ---------------- launcher ----------------
extern "C" void kernel_launch(void* const* d_in, const int* in_sizes, int n_in,
                              void* d_out, int out_size) {
    const float* x    = (const float*)d_in[0];
    const int*   eidx = (const int*)d_in[1];
    const float* sph  = (const float*)d_in[2];
    const float* Wr   = (const float*)d_in[3];
    const float* Wn   = (const float*)d_in[4];
    const float* Wq   = (const float*)d_in[5];
    const float* bq   = (const float*)d_in[6];
    const float* Wk   = (const float*)d_in[7];
    const float* bk   = (const float*)d_in[8];
    const float* Wv   = (const float*)d_in[9];
    const float* bv   = (const float*)d_in[10];
    const float* Wo   = (const float*)d_in[11];
    const float* bo   = (const float*)d_in[12];
    const float* W1   = (const float*)d_in[13];
    const float* b1   = (const float*)d_in[14];
    const float* W2   = (const float*)d_in[15];
    const float* b2   = (const float*)d_in[16];
    const float* ga1  = (const float*)d_in[17];
    const float* be1  = (const float*)d_in[18];
    const float* ga2  = (const float*)d_in[19];
    const float* be2  = (const float*)d_in[20];
    const float* ga3  = (const float*)d_in[21];
    const float* be3  = (const float*)d_in[22];
    float* out = (float*)d_out;

    float *p_xWn, *p_xr, *p_q, *p_k, *p_v, *p_o, *p_h2, *p_out0, *p_hid, *p_out1;
    float *p_ssum, *p_ssq;
    cudaGetSymbolAddress((void**)&p_xWn,  g_xWn);
    cudaGetSymbolAddress((void**)&p_xr,   g_xr);
    cudaGetSymbolAddress((void**)&p_q,    g_q);
    cudaGetSymbolAddress((void**)&p_k,    g_k);
    cudaGetSymbolAddress((void**)&p_v,    g_v);
    cudaGetSymbolAddress((void**)&p_o,    g_o);
    cudaGetSymbolAddress((void**)&p_h2,   g_h2);
    cudaGetSymbolAddress((void**)&p_out0, g_out0);
    cudaGetSymbolAddress((void**)&p_hid,  g_hid);
    cudaGetSymbolAddress((void**)&p_out1, g_out1);
    cudaGetSymbolAddress((void**)&p_ssum, g_ssum);
    cudaGetSymbolAddress((void**)&p_ssq,  g_ssq);

    const int elem4_blocks = (BNT*CCH/4 + 255) / 256;    // 2048

    zero_kernel<<<elem4_blocks, 256>>>();

    // merged projections: xWn, xr, q, k, v in one launch
    P5 p5;
    p5.B[0] = Wn; p5.B[1] = Wr; p5.B[2] = Wq; p5.B[3] = Wk; p5.B[4] = Wv;
    p5.bias[0] = nullptr; p5.bias[1] = nullptr;
    p5.bias[2] = bq; p5.bias[3] = bk; p5.bias[4] = bv;
    p5.C[0] = p_xWn; p5.C[1] = p_xr; p5.C[2] = p_q; p5.C[3] = p_k; p5.C[4] = p_v;
    proj_gemm_kernel<<<dim3(20, BNT/GBM), 256>>>(x, p5);

    // edge aggregation
    scatter_kernel<<<EE*64/256, 256>>>(eidx);

    // branch 1 pre-BN
    h1pre_kernel<<<elem4_blocks, 256>>>(x);

    // branch 2: attention + output projection (+x residual)
    attn_kernel<<<dim3(NNODE/64, HH, BB), 256>>>(sph);
    sgemm_kernel<<<dim3(CCH/GBN, BNT/GBM), 256>>>(p_o, Wo, bo, x, p_h2, CCH, CCH, 0);

    // fused stats for both branches
    colstats2_kernel<<<BNT/64, 256>>>();

    // combine BN branches
    bn_combine_kernel<<<elem4_blocks, 256>>>(ga1, be1, ga2, be2);

    // MLP
    sgemm_kernel<<<dim3(C2/GBN, BNT/GBM), 256>>>(p_out0, W1, b1, nullptr, p_hid, C2, CCH, 1);
    sgemm_kernel<<<dim3(CCH/GBN, BNT/GBM), 256>>>(p_hid, W2, b2, p_out0, p_out1, CCH, C2, 0);
    colstats_kernel<<<BNT/64, 256>>>(p_out1, p_ssum + 2*CCH, p_ssq + 2*CCH);

    // final BN
    bn_final_kernel<<<elem4_blocks, 256>>>(ga3, be3, out);
}

// round 5
// speedup vs baseline: 2.3835x; 1.2714x over previous
#include <cuda_runtime.h>
#include <cstdint>

// ---------------- problem constants ----------------
#define BNT   8192      // B*N nodes
#define CCH   256       // channels
#define BB    8
#define NNODE 1024
#define HH    8
#define DKK   32
#define EE    131072
#define C2    512
#define EPSB  1e-5f

// ---------------- device scratch ----------------
__device__ float g_xWn [BNT*CCH];
__device__ float g_xr  [BNT*CCH];
__device__ float g_q   [BNT*CCH];
__device__ float g_k   [BNT*CCH];
__device__ float g_v   [BNT*CCH];
__device__ float g_agg [BNT*CCH];
__device__ float g_h1  [BNT*CCH];
__device__ float g_o   [BNT*CCH];
__device__ float g_h2  [BNT*CCH];
__device__ float g_out0[BNT*CCH];
__device__ float g_hid [BNT*C2];
__device__ float g_out1[BNT*CCH];
__device__ float g_ssum[3][CCH];
__device__ float g_ssq [3][CCH];

// ---------------- zero scratch ----------------
__global__ void zero_kernel() {
    int idx = blockIdx.x * blockDim.x + threadIdx.x;
    if (idx < BNT*CCH/4) ((float4*)g_agg)[idx] = make_float4(0.f,0.f,0.f,0.f);
    if (idx < CCH) {
        #pragma unroll
        for (int s = 0; s < 3; s++) { g_ssum[s][idx] = 0.f; g_ssq[s][idx] = 0.f; }
    }
}

// =======================================================================
// tf32 tensor-core GEMM: 128x128 block, BK=16, 256 threads (8 warps),
// warp tile 64x32 = 4x4 m16n8k8 mma. Double-buffered smem.
// =======================================================================
#define TAPAD 20    // As stride (m-major): bank = (20*qr+qc)%32 bijective
#define TBPAD 136   // Bs stride (k-major): bank = (8*qc+qr)%32 bijective

__device__ __forceinline__ uint32_t f2tf(float x) {
    uint32_t y;
    asm volatile("cvt.rna.tf32.f32 %0, %1;" : "=r"(y) : "f"(x));
    return y;
}

__device__ __forceinline__ void mma8(float* d, const uint32_t* a, const uint32_t* b) {
    asm volatile(
        "mma.sync.aligned.m16n8k8.row.col.f32.tf32.tf32.f32 "
        "{%0,%1,%2,%3}, {%4,%5,%6,%7}, {%8,%9}, {%0,%1,%2,%3};\n"
        : "+f"(d[0]), "+f"(d[1]), "+f"(d[2]), "+f"(d[3])
        : "r"(a[0]), "r"(a[1]), "r"(a[2]), "r"(a[3]),
          "r"(b[0]), "r"(b[1]));
}

__device__ __forceinline__ void mma_gemm_core(
    const float* __restrict__ A, const float* __restrict__ Bm,
    const float* __restrict__ bias, const float* __restrict__ res,
    float* __restrict__ Cc, int N, int K, int block_row, int block_col, int relu,
    uint32_t (*As)[128][TAPAD], uint32_t (*Bs)[16][TBPAD])
{
    const int tid  = threadIdx.x;
    const int lane = tid & 31;
    const int w    = tid >> 5;
    const int wm   = (w >> 2) * 64;   // 0 or 64
    const int wn   = (w & 3) * 32;    // 0/32/64/96
    const int qr   = lane >> 2;       // 0..7
    const int qc   = lane & 3;        // 0..3

    // global->smem mapping
    const int aRow = tid >> 1;          // 0..127
    const int aK   = (tid & 1) * 8;     // 0 or 8
    const int bRow = tid >> 4;          // 0..15
    const int bCol = (tid & 15) * 8;    // 0..120

    const float* Aptr = A + (size_t)(block_row*128) * K;
    const float* Bptr = Bm + block_col*128;

    float acc[4][4][4];
    #pragma unroll
    for (int mi = 0; mi < 4; mi++)
        #pragma unroll
        for (int ni = 0; ni < 4; ni++)
            #pragma unroll
            for (int r = 0; r < 4; r++) acc[mi][ni][r] = 0.f;

    const int nstages = K >> 4;

    float4 ra0, ra1, rb0, rb1;

    // preload stage 0 into regs
    ra0 = *(const float4*)(Aptr + (size_t)aRow*K + aK);
    ra1 = *(const float4*)(Aptr + (size_t)aRow*K + aK + 4);
    rb0 = *(const float4*)(Bptr + (size_t)bRow*N + bCol);
    rb1 = *(const float4*)(Bptr + (size_t)bRow*N + bCol + 4);
    {
        uint4 u;
        u.x = f2tf(ra0.x); u.y = f2tf(ra0.y); u.z = f2tf(ra0.z); u.w = f2tf(ra0.w);
        *(uint4*)&As[0][aRow][aK] = u;
        u.x = f2tf(ra1.x); u.y = f2tf(ra1.y); u.z = f2tf(ra1.z); u.w = f2tf(ra1.w);
        *(uint4*)&As[0][aRow][aK + 4] = u;
        u.x = f2tf(rb0.x); u.y = f2tf(rb0.y); u.z = f2tf(rb0.z); u.w = f2tf(rb0.w);
        *(uint4*)&Bs[0][bRow][bCol] = u;
        u.x = f2tf(rb1.x); u.y = f2tf(rb1.y); u.z = f2tf(rb1.z); u.w = f2tf(rb1.w);
        *(uint4*)&Bs[0][bRow][bCol + 4] = u;
    }
    __syncthreads();

    for (int s = 0; s < nstages; s++) {
        const int buf = s & 1;
        const bool more = (s + 1 < nstages);
        if (more) {
            int k0 = (s + 1) << 4;
            ra0 = *(const float4*)(Aptr + (size_t)aRow*K + k0 + aK);
            ra1 = *(const float4*)(Aptr + (size_t)aRow*K + k0 + aK + 4);
            rb0 = *(const float4*)(Bptr + (size_t)(k0 + bRow)*N + bCol);
            rb1 = *(const float4*)(Bptr + (size_t)(k0 + bRow)*N + bCol + 4);
        }

        #pragma unroll
        for (int ks = 0; ks < 2; ks++) {
            const int kk = ks * 8;
            uint32_t af[4][4], bf[4][2];
            #pragma unroll
            for (int mi = 0; mi < 4; mi++) {
                int m = wm + mi*16 + qr;
                af[mi][0] = As[buf][m    ][kk + qc];
                af[mi][1] = As[buf][m + 8][kk + qc];
                af[mi][2] = As[buf][m    ][kk + qc + 4];
                af[mi][3] = As[buf][m + 8][kk + qc + 4];
            }
            #pragma unroll
            for (int ni = 0; ni < 4; ni++) {
                int n = wn + ni*8 + qr;
                bf[ni][0] = Bs[buf][kk + qc    ][n];
                bf[ni][1] = Bs[buf][kk + qc + 4][n];
            }
            #pragma unroll
            for (int mi = 0; mi < 4; mi++)
                #pragma unroll
                for (int ni = 0; ni < 4; ni++)
                    mma8(acc[mi][ni], af[mi], bf[ni]);
        }

        if (more) {
            const int nb = buf ^ 1;
            uint4 u;
            u.x = f2tf(ra0.x); u.y = f2tf(ra0.y); u.z = f2tf(ra0.z); u.w = f2tf(ra0.w);
            *(uint4*)&As[nb][aRow][aK] = u;
            u.x = f2tf(ra1.x); u.y = f2tf(ra1.y); u.z = f2tf(ra1.z); u.w = f2tf(ra1.w);
            *(uint4*)&As[nb][aRow][aK + 4] = u;
            u.x = f2tf(rb0.x); u.y = f2tf(rb0.y); u.z = f2tf(rb0.z); u.w = f2tf(rb0.w);
            *(uint4*)&Bs[nb][bRow][bCol] = u;
            u.x = f2tf(rb1.x); u.y = f2tf(rb1.y); u.z = f2tf(rb1.z); u.w = f2tf(rb1.w);
            *(uint4*)&Bs[nb][bRow][bCol + 4] = u;
        }
        __syncthreads();
    }

    // epilogue
    const int row0 = block_row*128 + wm;
    const int col0 = block_col*128 + wn;
    #pragma unroll
    for (int mi = 0; mi < 4; mi++) {
        #pragma unroll
        for (int half = 0; half < 2; half++) {
            const int r = row0 + mi*16 + qr + half*8;
            #pragma unroll
            for (int ni = 0; ni < 4; ni++) {
                const int c = col0 + ni*8 + 2*qc;
                float v0 = acc[mi][ni][half*2 + 0];
                float v1 = acc[mi][ni][half*2 + 1];
                if (bias) { v0 += bias[c]; v1 += bias[c+1]; }
                if (res) {
                    float2 rv = *(const float2*)(res + (size_t)r*N + c);
                    v0 += rv.x; v1 += rv.y;
                }
                if (relu) { v0 = fmaxf(v0, 0.f); v1 = fmaxf(v1, 0.f); }
                *(float2*)(Cc + (size_t)r*N + c) = make_float2(v0, v1);
            }
        }
    }
}

// ---------------- generic GEMM (Wo, MLP) ----------------
__global__ __launch_bounds__(256, 2)
void sgemm_kernel(const float* __restrict__ A, const float* __restrict__ Bm,
                  const float* __restrict__ bias, const float* __restrict__ res,
                  float* __restrict__ Cc, int N, int K, int relu)
{
    __shared__ uint32_t As[2][128][TAPAD];
    __shared__ uint32_t Bs[2][16][TBPAD];
    mma_gemm_core(A, Bm, bias, res, Cc, N, K, blockIdx.y, blockIdx.x, relu, As, Bs);
}

// ---------------- merged 5-way projection GEMM ----------------
struct P5 {
    const float* B[5];
    const float* bias[5];
    float*       C[5];
};

__global__ __launch_bounds__(256, 2)
void proj_gemm_kernel(const float* __restrict__ A, P5 p)
{
    __shared__ uint32_t As[2][128][TAPAD];
    __shared__ uint32_t Bs[2][16][TBPAD];
    const int bw = blockIdx.x >> 1;       // which weight (0..4)
    const int bc = blockIdx.x & 1;        // which 128-col half
    mma_gemm_core(A, p.B[bw], p.bias[bw], nullptr, p.C[bw],
                  CCH, CCH, blockIdx.y, bc, 0, As, Bs);
}

// ---------------- edge scatter: agg[dst] += xWn[src] ----------------
__global__ void scatter_kernel(const int* __restrict__ ei) {
    int t = blockIdx.x * blockDim.x + threadIdx.x;
    if (t >= EE*64) return;
    int e = t >> 6;
    int j = (t & 63) * 4;
    int src = ei[e];
    int dst = ei[EE + e];
    float4 mv = *(const float4*)(g_xWn + (long long)src*CCH + j);
    float* p = g_agg + (long long)dst*CCH + j;
    atomicAdd(p+0, mv.x);
    atomicAdd(p+1, mv.y);
    atomicAdd(p+2, mv.z);
    atomicAdd(p+3, mv.w);
}

// ---------------- h1pre = x@Wr + agg + x ----------------
__global__ void h1pre_kernel(const float* __restrict__ x) {
    int idx = blockIdx.x * blockDim.x + threadIdx.x;
    if (idx >= BNT*CCH/4) return;
    float4 a = ((const float4*)g_xr)[idx];
    float4 g = ((const float4*)g_agg)[idx];
    float4 xv = ((const float4*)x)[idx];
    a.x += g.x + xv.x; a.y += g.y + xv.y;
    a.z += g.z + xv.z; a.w += g.w + xv.w;
    ((float4*)g_h1)[idx] = a;
}

// ---------------- per-column stats: h1 -> slot0, h2 -> slot1 (fused) ---
__global__ void colstats2_kernel() {
    int c = threadIdx.x;
    long long r0 = (long long)blockIdx.x * 64;
    float s1 = 0.f, q1 = 0.f, s2 = 0.f, q2 = 0.f;
    #pragma unroll 4
    for (int rr = 0; rr < 64; rr++) {
        float v1 = g_h1[(r0 + rr)*CCH + c];
        float v2 = g_h2[(r0 + rr)*CCH + c];
        s1 += v1; q1 += v1 * v1;
        s2 += v2; q2 += v2 * v2;
    }
    atomicAdd(&g_ssum[0][c], s1);
    atomicAdd(&g_ssq [0][c], q1);
    atomicAdd(&g_ssum[1][c], s2);
    atomicAdd(&g_ssq [1][c], q2);
}

__global__ void colstats_kernel(const float* __restrict__ X,
                                float* __restrict__ ssum, float* __restrict__ ssq) {
    int c = threadIdx.x;
    long long r0 = (long long)blockIdx.x * 64;
    float s = 0.f, q = 0.f;
    #pragma unroll 4
    for (int rr = 0; rr < 64; rr++) {
        float v = X[(r0 + rr)*CCH + c];
        s += v; q += v * v;
    }
    atomicAdd(&ssum[c], s);
    atomicAdd(&ssq[c], q);
}

// =======================================================================
// Attention with sph modulation (SIMT, no max subtraction, transposed smem)
// grid: (N/64, H, B), 256 threads
// =======================================================================
__global__ __launch_bounds__(256, 2)
void attn_kernel(const float* __restrict__ sph) {
    __shared__ float Qt[DKK][68];   // [k][row]
    __shared__ float Kt[DKK][68];   // [k][col j]
    __shared__ float Vt[DKK][76];   // [d][col j]
    __shared__ float Ps[64][64];    // [row][j]
    __shared__ float lsum[64];

    const int i0   = blockIdx.x * 64;
    const int h    = blockIdx.y;
    const int b    = blockIdx.z;
    const int tid  = threadIdx.x;
    const int lane = tid & 31;
    const int w    = tid >> 5;

    const int tr4 = (tid >> 4) * 4;   // rows tr4..tr4+3 (QK phase)
    const int tc4 = (tid & 15) * 4;   // cols tc4..tc4+3 (QK phase)

    const long long base = (long long)b*NNODE*CCH + h*DKK;
    const float rscale = 0.17677669529663688f;  // 1/sqrt(32)

    for (int idx = tid; idx < 64*DKK; idx += 256) {
        int r = idx >> 5, c = idx & 31;
        Qt[c][r] = g_q[base + (long long)(i0 + r)*CCH + c];
    }

    float acc[8];
    float rs[4];
    #pragma unroll
    for (int r = 0; r < 8; r++) acc[r] = 0.f;
    #pragma unroll
    for (int u = 0; u < 4; u++) rs[u] = 0.f;

    for (int jt = 0; jt < NNODE; jt += 64) {
        __syncthreads();
        for (int idx = tid; idx < 64*DKK; idx += 256) {
            int r = idx >> 5, c = idx & 31;
            Kt[c][r] = g_k[base + (long long)(jt + r)*CCH + c];
            Vt[c][r] = g_v[base + (long long)(jt + r)*CCH + c];
        }
        __syncthreads();

        float a4[4][4];
        #pragma unroll
        for (int u = 0; u < 4; u++)
            #pragma unroll
            for (int vv = 0; vv < 4; vv++) a4[u][vv] = 0.f;

        #pragma unroll
        for (int kk = 0; kk < DKK; kk++) {
            float4 qa = *(const float4*)&Qt[kk][tr4];
            float4 kb = *(const float4*)&Kt[kk][tc4];
            float ra[4] = {qa.x, qa.y, qa.z, qa.w};
            float rb[4] = {kb.x, kb.y, kb.z, kb.w};
            #pragma unroll
            for (int u = 0; u < 4; u++)
                #pragma unroll
                for (int vv = 0; vv < 4; vv++)
                    a4[u][vv] += ra[u] * rb[vv];
        }

        #pragma unroll
        for (int u = 0; u < 4; u++) {
            float4 s4 = *(const float4*)(sph +
                ((long long)b*NNODE + i0 + tr4 + u)*NNODE + jt + tc4);
            float p0 = __expf(a4[u][0] * rscale * s4.x);
            float p1 = __expf(a4[u][1] * rscale * s4.y);
            float p2 = __expf(a4[u][2] * rscale * s4.z);
            float p3 = __expf(a4[u][3] * rscale * s4.w);
            rs[u] += (p0 + p1) + (p2 + p3);
            *(float4*)&Ps[tr4 + u][tc4] = make_float4(p0, p1, p2, p3);
        }
        __syncthreads();

        #pragma unroll
        for (int jj = 0; jj < 64; jj += 4) {
            float4 v4 = *(const float4*)&Vt[lane][jj];
            #pragma unroll
            for (int r = 0; r < 8; r++) {
                float4 p4 = *(const float4*)&Ps[w*8 + r][jj];
                acc[r] += p4.x*v4.x + p4.y*v4.y + p4.z*v4.z + p4.w*v4.w;
            }
        }
    }

    #pragma unroll
    for (int u = 0; u < 4; u++) {
        #pragma unroll
        for (int off = 1; off < 16; off <<= 1)
            rs[u] += __shfl_xor_sync(0xffffffffu, rs[u], off);
    }
    if ((tid & 15) == 0) {
        #pragma unroll
        for (int u = 0; u < 4; u++) lsum[tr4 + u] = rs[u];
    }
    __syncthreads();

    #pragma unroll
    for (int r = 0; r < 8; r++) {
        int i = i0 + w*8 + r;
        g_o[((long long)b*NNODE + i)*CCH + h*DKK + lane] = acc[r] / lsum[w*8 + r];
    }
}

// ---------------- out0 = BN1(h1) + BN2(h2) ----------------
__global__ void bn_combine_kernel(const float* __restrict__ ga1, const float* __restrict__ be1,
                                  const float* __restrict__ ga2, const float* __restrict__ be2) {
    int idx = blockIdx.x * blockDim.x + threadIdx.x;
    if (idx >= BNT*CCH/4) return;
    int c0 = (idx << 2) & (CCH - 1);
    float4 a = ((const float4*)g_h1)[idx];
    float4 bb = ((const float4*)g_h2)[idx];
    float av[4] = {a.x, a.y, a.z, a.w};
    float bv[4] = {bb.x, bb.y, bb.z, bb.w};
    float ov[4];
    const float inv_n = 1.f / (float)BNT;
    #pragma unroll
    for (int j = 0; j < 4; j++) {
        int c = c0 + j;
        float m1 = g_ssum[0][c] * inv_n;
        float v1 = g_ssq[0][c] * inv_n - m1*m1;
        float i1 = rsqrtf(v1 + EPSB);
        float m2 = g_ssum[1][c] * inv_n;
        float v2 = g_ssq[1][c] * inv_n - m2*m2;
        float i2 = rsqrtf(v2 + EPSB);
        ov[j] = (av[j]-m1)*i1*ga1[c] + be1[c] + (bv[j]-m2)*i2*ga2[c] + be2[c];
    }
    ((float4*)g_out0)[idx] = make_float4(ov[0], ov[1], ov[2], ov[3]);
}

// ---------------- final BN3 -> output ----------------
__global__ void bn_final_kernel(const float* __restrict__ ga3, const float* __restrict__ be3,
                                float* __restrict__ out) {
    int idx = blockIdx.x * blockDim.x + threadIdx.x;
    if (idx >= BNT*CCH/4) return;
    int c0 = (idx << 2) & (CCH - 1);
    float4 a = ((const float4*)g_out1)[idx];
    float av[4] = {a.x, a.y, a.z, a.w};
    float ov[4];
    const float inv_n = 1.f / (float)BNT;
    #pragma unroll
    for (int j = 0; j < 4; j++) {
        int c = c0 + j;
        float m3 = g_ssum[2][c] * inv_n;
        float v3 = g_ssq[2][c] * inv_n - m3*m3;
        float i3 = rsqrtf(v3 + EPSB);
        ov[j] = (av[j]-m3)*i3*ga3[c] + be3[c];
    }
    ((float4*)out)[idx] = make_float4(ov[0], ov[1], ov[2], ov[3]);
}

// ---------------- launcher ----------------
extern "C" void kernel_launch(void* const* d_in, const int* in_sizes, int n_in,
                              void* d_out, int out_size) {
    const float* x    = (const float*)d_in[0];
    const int*   eidx = (const int*)d_in[1];
    const float* sph  = (const float*)d_in[2];
    const float* Wr   = (const float*)d_in[3];
    const float* Wn   = (const float*)d_in[4];
    const float* Wq   = (const float*)d_in[5];
    const float* bq   = (const float*)d_in[6];
    const float* Wk   = (const float*)d_in[7];
    const float* bk   = (const float*)d_in[8];
    const float* Wv   = (const float*)d_in[9];
    const float* bv   = (const float*)d_in[10];
    const float* Wo   = (const float*)d_in[11];
    const float* bo   = (const float*)d_in[12];
    const float* W1   = (const float*)d_in[13];
    const float* b1   = (const float*)d_in[14];
    const float* W2   = (const float*)d_in[15];
    const float* b2   = (const float*)d_in[16];
    const float* ga1  = (const float*)d_in[17];
    const float* be1  = (const float*)d_in[18];
    const float* ga2  = (const float*)d_in[19];
    const float* be2  = (const float*)d_in[20];
    const float* ga3  = (const float*)d_in[21];
    const float* be3  = (const float*)d_in[22];
    float* out = (float*)d_out;

    float *p_xWn, *p_xr, *p_q, *p_k, *p_v, *p_o, *p_h2, *p_out0, *p_hid, *p_out1;
    float *p_ssum, *p_ssq;
    cudaGetSymbolAddress((void**)&p_xWn,  g_xWn);
    cudaGetSymbolAddress((void**)&p_xr,   g_xr);
    cudaGetSymbolAddress((void**)&p_q,    g_q);
    cudaGetSymbolAddress((void**)&p_k,    g_k);
    cudaGetSymbolAddress((void**)&p_v,    g_v);
    cudaGetSymbolAddress((void**)&p_o,    g_o);
    cudaGetSymbolAddress((void**)&p_h2,   g_h2);
    cudaGetSymbolAddress((void**)&p_out0, g_out0);
    cudaGetSymbolAddress((void**)&p_hid,  g_hid);
    cudaGetSymbolAddress((void**)&p_out1, g_out1);
    cudaGetSymbolAddress((void**)&p_ssum, g_ssum);
    cudaGetSymbolAddress((void**)&p_ssq,  g_ssq);

    const int elem4_blocks = (BNT*CCH/4 + 255) / 256;    // 2048

    zero_kernel<<<elem4_blocks, 256>>>();

    // merged projections: xWn, xr, q, k, v in one launch
    P5 p5;
    p5.B[0] = Wn; p5.B[1] = Wr; p5.B[2] = Wq; p5.B[3] = Wk; p5.B[4] = Wv;
    p5.bias[0] = nullptr; p5.bias[1] = nullptr;
    p5.bias[2] = bq; p5.bias[3] = bk; p5.bias[4] = bv;
    p5.C[0] = p_xWn; p5.C[1] = p_xr; p5.C[2] = p_q; p5.C[3] = p_k; p5.C[4] = p_v;
    proj_gemm_kernel<<<dim3(10, BNT/128), 256>>>(x, p5);

    // edge aggregation
    scatter_kernel<<<EE*64/256, 256>>>(eidx);

    // branch 1 pre-BN
    h1pre_kernel<<<elem4_blocks, 256>>>(x);

    // branch 2: attention + output projection (+x residual)
    attn_kernel<<<dim3(NNODE/64, HH, BB), 256>>>(sph);
    sgemm_kernel<<<dim3(CCH/128, BNT/128), 256>>>(p_o, Wo, bo, x, p_h2, CCH, CCH, 0);

    // fused stats for both branches
    colstats2_kernel<<<BNT/64, 256>>>();

    // combine BN branches
    bn_combine_kernel<<<elem4_blocks, 256>>>(ga1, be1, ga2, be2);

    // MLP
    sgemm_kernel<<<dim3(C2/128, BNT/128), 256>>>(p_out0, W1, b1, nullptr, p_hid, C2, CCH, 1);
    sgemm_kernel<<<dim3(CCH/128, BNT/128), 256>>>(p_hid, W2, b2, p_out0, p_out1, CCH, C2, 0);
    colstats_kernel<<<BNT/64, 256>>>(p_out1, p_ssum + 2*CCH, p_ssq + 2*CCH);

    // final BN
    bn_final_kernel<<<elem4_blocks, 256>>>(ga3, be3, out);
}

// round 6
// speedup vs baseline: 3.4924x; 1.4652x over previous
#include <cuda_runtime.h>
#include <cstdint>

// ---------------- problem constants ----------------
#define BNT   8192      // B*N nodes
#define CCH   256       // channels
#define BB    8
#define NNODE 1024
#define HH    8
#define DKK   32
#define EE    131072
#define C2    512
#define EPSB  1e-5f

// ---------------- device scratch ----------------
__device__ float g_xWn [BNT*CCH];
__device__ float g_q   [BNT*CCH];
__device__ float g_k   [BNT*CCH];
__device__ float g_v   [BNT*CCH];
__device__ float g_agg [BNT*CCH];   // becomes h1 = x@Wr + x + segsum
__device__ float g_o   [BNT*CCH];
__device__ float g_h2  [BNT*CCH];
__device__ float g_out0[BNT*CCH];
__device__ float g_hid [BNT*C2];
__device__ float g_out1[BNT*CCH];
__device__ float g_ssum[3][CCH];
__device__ float g_ssq [3][CCH];

// ---------------- zero stats ----------------
__global__ void zero_stats_kernel() {
    int c = threadIdx.x;
    #pragma unroll
    for (int s = 0; s < 3; s++) { g_ssum[s][c] = 0.f; g_ssq[s][c] = 0.f; }
}

// =======================================================================
// tf32 tensor-core GEMM: 128x128 block, BK=16, 256 threads (8 warps),
// warp tile 64x32 = 4x4 m16n8k8 mma. Double-buffered smem.
// =======================================================================
#define TAPAD 20
#define TBPAD 136

__device__ __forceinline__ uint32_t f2tf(float x) {
    uint32_t y;
    asm volatile("cvt.rna.tf32.f32 %0, %1;" : "=r"(y) : "f"(x));
    return y;
}

__device__ __forceinline__ void mma8(float* d, const uint32_t* a, const uint32_t* b) {
    asm volatile(
        "mma.sync.aligned.m16n8k8.row.col.f32.tf32.tf32.f32 "
        "{%0,%1,%2,%3}, {%4,%5,%6,%7}, {%8,%9}, {%0,%1,%2,%3};\n"
        : "+f"(d[0]), "+f"(d[1]), "+f"(d[2]), "+f"(d[3])
        : "r"(a[0]), "r"(a[1]), "r"(a[2]), "r"(a[3]),
          "r"(b[0]), "r"(b[1]));
}

__device__ __forceinline__ void mma_gemm_core(
    const float* __restrict__ A, const float* __restrict__ Bm,
    const float* __restrict__ bias, const float* __restrict__ res,
    float* __restrict__ Cc, int N, int K, int block_row, int block_col, int relu,
    uint32_t (*As)[128][TAPAD], uint32_t (*Bs)[16][TBPAD])
{
    const int tid  = threadIdx.x;
    const int lane = tid & 31;
    const int w    = tid >> 5;
    const int wm   = (w >> 2) * 64;
    const int wn   = (w & 3) * 32;
    const int qr   = lane >> 2;
    const int qc   = lane & 3;

    const int aRow = tid >> 1;
    const int aK   = (tid & 1) * 8;
    const int bRow = tid >> 4;
    const int bCol = (tid & 15) * 8;

    const float* Aptr = A + (size_t)(block_row*128) * K;
    const float* Bptr = Bm + block_col*128;

    float acc[4][4][4];
    #pragma unroll
    for (int mi = 0; mi < 4; mi++)
        #pragma unroll
        for (int ni = 0; ni < 4; ni++)
            #pragma unroll
            for (int r = 0; r < 4; r++) acc[mi][ni][r] = 0.f;

    const int nstages = K >> 4;
    float4 ra0, ra1, rb0, rb1;

    ra0 = *(const float4*)(Aptr + (size_t)aRow*K + aK);
    ra1 = *(const float4*)(Aptr + (size_t)aRow*K + aK + 4);
    rb0 = *(const float4*)(Bptr + (size_t)bRow*N + bCol);
    rb1 = *(const float4*)(Bptr + (size_t)bRow*N + bCol + 4);
    {
        uint4 u;
        u.x = f2tf(ra0.x); u.y = f2tf(ra0.y); u.z = f2tf(ra0.z); u.w = f2tf(ra0.w);
        *(uint4*)&As[0][aRow][aK] = u;
        u.x = f2tf(ra1.x); u.y = f2tf(ra1.y); u.z = f2tf(ra1.z); u.w = f2tf(ra1.w);
        *(uint4*)&As[0][aRow][aK + 4] = u;
        u.x = f2tf(rb0.x); u.y = f2tf(rb0.y); u.z = f2tf(rb0.z); u.w = f2tf(rb0.w);
        *(uint4*)&Bs[0][bRow][bCol] = u;
        u.x = f2tf(rb1.x); u.y = f2tf(rb1.y); u.z = f2tf(rb1.z); u.w = f2tf(rb1.w);
        *(uint4*)&Bs[0][bRow][bCol + 4] = u;
    }
    __syncthreads();

    for (int s = 0; s < nstages; s++) {
        const int buf = s & 1;
        const bool more = (s + 1 < nstages);
        if (more) {
            int k0 = (s + 1) << 4;
            ra0 = *(const float4*)(Aptr + (size_t)aRow*K + k0 + aK);
            ra1 = *(const float4*)(Aptr + (size_t)aRow*K + k0 + aK + 4);
            rb0 = *(const float4*)(Bptr + (size_t)(k0 + bRow)*N + bCol);
            rb1 = *(const float4*)(Bptr + (size_t)(k0 + bRow)*N + bCol + 4);
        }

        #pragma unroll
        for (int ks = 0; ks < 2; ks++) {
            const int kk = ks * 8;
            uint32_t af[4][4], bf[4][2];
            #pragma unroll
            for (int mi = 0; mi < 4; mi++) {
                int m = wm + mi*16 + qr;
                af[mi][0] = As[buf][m    ][kk + qc];
                af[mi][1] = As[buf][m + 8][kk + qc];
                af[mi][2] = As[buf][m    ][kk + qc + 4];
                af[mi][3] = As[buf][m + 8][kk + qc + 4];
            }
            #pragma unroll
            for (int ni = 0; ni < 4; ni++) {
                int n = wn + ni*8 + qr;
                bf[ni][0] = Bs[buf][kk + qc    ][n];
                bf[ni][1] = Bs[buf][kk + qc + 4][n];
            }
            #pragma unroll
            for (int mi = 0; mi < 4; mi++)
                #pragma unroll
                for (int ni = 0; ni < 4; ni++)
                    mma8(acc[mi][ni], af[mi], bf[ni]);
        }

        if (more) {
            const int nb = buf ^ 1;
            uint4 u;
            u.x = f2tf(ra0.x); u.y = f2tf(ra0.y); u.z = f2tf(ra0.z); u.w = f2tf(ra0.w);
            *(uint4*)&As[nb][aRow][aK] = u;
            u.x = f2tf(ra1.x); u.y = f2tf(ra1.y); u.z = f2tf(ra1.z); u.w = f2tf(ra1.w);
            *(uint4*)&As[nb][aRow][aK + 4] = u;
            u.x = f2tf(rb0.x); u.y = f2tf(rb0.y); u.z = f2tf(rb0.z); u.w = f2tf(rb0.w);
            *(uint4*)&Bs[nb][bRow][bCol] = u;
            u.x = f2tf(rb1.x); u.y = f2tf(rb1.y); u.z = f2tf(rb1.z); u.w = f2tf(rb1.w);
            *(uint4*)&Bs[nb][bRow][bCol + 4] = u;
        }
        __syncthreads();
    }

    const int row0 = block_row*128 + wm;
    const int col0 = block_col*128 + wn;
    #pragma unroll
    for (int mi = 0; mi < 4; mi++) {
        #pragma unroll
        for (int half = 0; half < 2; half++) {
            const int r = row0 + mi*16 + qr + half*8;
            #pragma unroll
            for (int ni = 0; ni < 4; ni++) {
                const int c = col0 + ni*8 + 2*qc;
                float v0 = acc[mi][ni][half*2 + 0];
                float v1 = acc[mi][ni][half*2 + 1];
                if (bias) { v0 += bias[c]; v1 += bias[c+1]; }
                if (res) {
                    float2 rv = *(const float2*)(res + (size_t)r*N + c);
                    v0 += rv.x; v1 += rv.y;
                }
                if (relu) { v0 = fmaxf(v0, 0.f); v1 = fmaxf(v1, 0.f); }
                *(float2*)(Cc + (size_t)r*N + c) = make_float2(v0, v1);
            }
        }
    }
}

// ---------------- generic GEMM (Wo, MLP) ----------------
__global__ __launch_bounds__(256, 2)
void sgemm_kernel(const float* __restrict__ A, const float* __restrict__ Bm,
                  const float* __restrict__ bias, const float* __restrict__ res,
                  float* __restrict__ Cc, int N, int K, int relu)
{
    __shared__ uint32_t As[2][128][TAPAD];
    __shared__ uint32_t Bs[2][16][TBPAD];
    mma_gemm_core(A, Bm, bias, res, Cc, N, K, blockIdx.y, blockIdx.x, relu, As, Bs);
}

// ---------------- merged 5-way projection GEMM ----------------
struct P5 {
    const float* B[5];
    const float* bias[5];
    const float* res[5];
    float*       C[5];
};

__global__ __launch_bounds__(256, 2)
void proj_gemm_kernel(const float* __restrict__ A, P5 p)
{
    __shared__ uint32_t As[2][128][TAPAD];
    __shared__ uint32_t Bs[2][16][TBPAD];
    const int bw = blockIdx.x >> 1;
    const int bc = blockIdx.x & 1;
    mma_gemm_core(A, p.B[bw], p.bias[bw], p.res[bw], p.C[bw],
                  CCH, CCH, blockIdx.y, bc, 0, As, Bs);
}

// ---------------- edge scatter: agg[dst] += xWn[src] ----------------
__global__ void scatter_kernel(const int* __restrict__ ei) {
    int t = blockIdx.x * blockDim.x + threadIdx.x;
    if (t >= EE*64) return;
    int e = t >> 6;
    int j = (t & 63) * 4;
    int src = ei[e];
    int dst = ei[EE + e];
    float4 mv = *(const float4*)(g_xWn + (size_t)src*CCH + j);
    float* p = g_agg + (size_t)dst*CCH + j;
    atomicAdd(p+0, mv.x);
    atomicAdd(p+1, mv.y);
    atomicAdd(p+2, mv.z);
    atomicAdd(p+3, mv.w);
}

// ---------------- per-column stats: agg(h1) -> slot0, h2 -> slot1 ------
__global__ void colstats2_kernel() {
    int c = threadIdx.x;
    size_t r0 = (size_t)blockIdx.x * 64;
    float s1 = 0.f, q1 = 0.f, s2 = 0.f, q2 = 0.f;
    #pragma unroll 4
    for (int rr = 0; rr < 64; rr++) {
        float v1 = g_agg[(r0 + rr)*CCH + c];
        float v2 = g_h2[(r0 + rr)*CCH + c];
        s1 += v1; q1 += v1 * v1;
        s2 += v2; q2 += v2 * v2;
    }
    atomicAdd(&g_ssum[0][c], s1);
    atomicAdd(&g_ssq [0][c], q1);
    atomicAdd(&g_ssum[1][c], s2);
    atomicAdd(&g_ssq [1][c], q2);
}

__global__ void colstats_kernel(const float* __restrict__ X,
                                float* __restrict__ ssum, float* __restrict__ ssq) {
    int c = threadIdx.x;
    size_t r0 = (size_t)blockIdx.x * 64;
    float s = 0.f, q = 0.f;
    #pragma unroll 4
    for (int rr = 0; rr < 64; rr++) {
        float v = X[(r0 + rr)*CCH + c];
        s += v; q += v * v;
    }
    atomicAdd(&ssum[c], s);
    atomicAdd(&ssq[c], q);
}

// =======================================================================
// tf32 mma attention. Computes S^T = K Q^T per chunk (K in natural layout,
// Q transposed once). P stored transposed Pt[j][i] = exactly the A-operand
// layout PV needs. V natural layout = B-operand layout. Non-online softmax
// (bounded scores): O accumulates unnormalized, one rowsum divide at end.
// grid: (N/128, H, B), 256 threads, dynamic smem.
// =======================================================================
#define QTS 136   // Qt row stride (words): 136%32=8 -> (8qc+qr) bijective
#define KSS 36    // Ks row stride: 36%32=4  -> (4qr+qc) bijective
#define VTS 40    // Vt row stride: 40%32=8  -> (8qc+qr) bijective
#define PTS 136   // Pt row stride
#define ATT_SMEM_WORDS (32*QTS + 64*KSS + 64*VTS + 64*PTS + 128)
#define ATT_SMEM_BYTES (ATT_SMEM_WORDS*4)

__global__ __launch_bounds__(256, 2)
void attn_mma_kernel(const float* __restrict__ sph) {
    extern __shared__ uint32_t smem[];
    uint32_t* Qt = smem;                       // [32][QTS]  tf32
    uint32_t* Ks = Qt + 32*QTS;                // [64][KSS]  tf32
    uint32_t* Vt = Ks + 64*KSS;                // [64][VTS]  tf32
    uint32_t* Pt = Vt + 64*VTS;                // [64][PTS]  tf32
    float*  lsum = (float*)(Pt + 64*PTS);      // [128]

    const int i0   = blockIdx.x * 128;
    const int h    = blockIdx.y;
    const int b    = blockIdx.z;
    const int tid  = threadIdx.x;
    const int lane = tid & 31;
    const int w    = tid >> 5;
    const int qr   = lane >> 2;
    const int qc   = lane & 3;

    const size_t base = (size_t)b*NNODE*CCH + h*DKK;
    const float rscale = 0.17677669529663688f;  // 1/sqrt(32)

    // Q transposed into smem (once)
    for (int idx = tid; idx < 128*8; idx += 256) {
        int i = idx >> 3, c4 = (idx & 7) * 4;
        float4 qv = *(const float4*)(g_q + base + (size_t)(i0+i)*CCH + c4);
        Qt[(c4+0)*QTS + i] = f2tf(qv.x);
        Qt[(c4+1)*QTS + i] = f2tf(qv.y);
        Qt[(c4+2)*QTS + i] = f2tf(qv.z);
        Qt[(c4+3)*QTS + i] = f2tf(qv.w);
    }
    if (tid < 128) lsum[tid] = 0.f;

    float oc[4][4];     // PV accum: 4 d-frags
    float rs[8][2];     // rowsum partials per q n-frag
    #pragma unroll
    for (int a = 0; a < 4; a++)
        #pragma unroll
        for (int r = 0; r < 4; r++) oc[a][r] = 0.f;
    #pragma unroll
    for (int a = 0; a < 8; a++) { rs[a][0] = 0.f; rs[a][1] = 0.f; }

    const int m0k = (w & 3) * 16;   // QK: key m-tile
    const int nbq = (w >> 2) * 64;  // QK: q n-range (64 cols)
    const int m0o = w * 16;         // PV: q-row m-tile

    const float* sphb = sph + ((size_t)b*NNODE + i0)*NNODE;

    for (int jt = 0; jt < NNODE; jt += 64) {
        __syncthreads();   // prev PV done: Ks/Vt/Pt free
        for (int idx = tid; idx < 64*8; idx += 256) {
            int j = idx >> 3, c4 = (idx & 7) * 4;
            float4 kv = *(const float4*)(g_k + base + (size_t)(jt+j)*CCH + c4);
            float4 vv = *(const float4*)(g_v + base + (size_t)(jt+j)*CCH + c4);
            uint4 ku; ku.x = f2tf(kv.x); ku.y = f2tf(kv.y); ku.z = f2tf(kv.z); ku.w = f2tf(kv.w);
            *(uint4*)&Ks[j*KSS + c4] = ku;
            uint4 vu; vu.x = f2tf(vv.x); vu.y = f2tf(vv.y); vu.z = f2tf(vv.z); vu.w = f2tf(vv.w);
            *(uint4*)&Vt[j*VTS + c4] = vu;
        }
        __syncthreads();

        // ---- S^T = K Q^T ----
        float sc[8][4];
        #pragma unroll
        for (int ni = 0; ni < 8; ni++)
            #pragma unroll
            for (int r = 0; r < 4; r++) sc[ni][r] = 0.f;

        #pragma unroll
        for (int ks = 0; ks < 4; ks++) {
            const int kk = ks * 8;
            uint32_t af[4];
            af[0] = Ks[(m0k+qr  )*KSS + kk+qc];
            af[1] = Ks[(m0k+qr+8)*KSS + kk+qc];
            af[2] = Ks[(m0k+qr  )*KSS + kk+qc+4];
            af[3] = Ks[(m0k+qr+8)*KSS + kk+qc+4];
            #pragma unroll
            for (int ni = 0; ni < 8; ni++) {
                const int n0 = nbq + ni*8;
                uint32_t bf[2];
                bf[0] = Qt[(kk+qc  )*QTS + n0+qr];
                bf[1] = Qt[(kk+qc+4)*QTS + n0+qr];
                mma8(sc[ni], af, bf);
            }
        }

        // ---- exp(sc * rscale * sph) -> Pt, rowsums ----
        #pragma unroll
        for (int ni = 0; ni < 8; ni++) {
            const int iA = nbq + ni*8 + 2*qc;    // q index (and +1)
            const int jA = m0k + qr;             // key index (and +8)
            const float* s0p = sphb + (size_t)iA*NNODE + jt + jA;
            float sp00 = s0p[0];
            float sp08 = s0p[8];
            float sp10 = s0p[NNODE];
            float sp18 = s0p[NNODE + 8];
            float p0 = __expf(sc[ni][0] * rscale * sp00);
            float p1 = __expf(sc[ni][1] * rscale * sp10);
            float p2 = __expf(sc[ni][2] * rscale * sp08);
            float p3 = __expf(sc[ni][3] * rscale * sp18);
            rs[ni][0] += p0 + p2;
            rs[ni][1] += p1 + p3;
            uint2 w0; w0.x = f2tf(p0); w0.y = f2tf(p1);
            uint2 w1; w1.x = f2tf(p2); w1.y = f2tf(p3);
            *(uint2*)&Pt[(size_t)jA*PTS + iA] = w0;
            *(uint2*)&Pt[(size_t)(jA+8)*PTS + iA] = w1;
        }
        __syncthreads();   // Pt ready

        // ---- O += P V ----
        #pragma unroll
        for (int ks = 0; ks < 8; ks++) {
            const int kk = ks * 8;
            uint32_t af[4];
            af[0] = Pt[(kk+qc  )*PTS + m0o+qr];
            af[1] = Pt[(kk+qc  )*PTS + m0o+qr+8];
            af[2] = Pt[(kk+qc+4)*PTS + m0o+qr];
            af[3] = Pt[(kk+qc+4)*PTS + m0o+qr+8];
            #pragma unroll
            for (int nf = 0; nf < 4; nf++) {
                uint32_t bf[2];
                bf[0] = Vt[(kk+qc  )*VTS + nf*8+qr];
                bf[1] = Vt[(kk+qc+4)*VTS + nf*8+qr];
                mma8(oc[nf], af, bf);
            }
        }
    }

    // ---- rowsum reduce (over qr lanes), accumulate across warps ----
    #pragma unroll
    for (int ni = 0; ni < 8; ni++) {
        #pragma unroll
        for (int e = 0; e < 2; e++) {
            float v = rs[ni][e];
            v += __shfl_xor_sync(0xffffffffu, v, 4);
            v += __shfl_xor_sync(0xffffffffu, v, 8);
            v += __shfl_xor_sync(0xffffffffu, v, 16);
            rs[ni][e] = v;
        }
    }
    if (qr == 0) {
        #pragma unroll
        for (int ni = 0; ni < 8; ni++) {
            atomicAdd(&lsum[nbq + ni*8 + 2*qc    ], rs[ni][0]);
            atomicAdd(&lsum[nbq + ni*8 + 2*qc + 1], rs[ni][1]);
        }
    }
    __syncthreads();

    // ---- normalize + write O ----
    {
        const int iA = m0o + qr;
        const float inv0 = 1.f / lsum[iA];
        const float inv8 = 1.f / lsum[iA + 8];
        #pragma unroll
        for (int nf = 0; nf < 4; nf++) {
            const int d = nf*8 + 2*qc;
            *(float2*)(g_o + ((size_t)b*NNODE + i0 + iA)*CCH + h*DKK + d) =
                make_float2(oc[nf][0]*inv0, oc[nf][1]*inv0);
            *(float2*)(g_o + ((size_t)b*NNODE + i0 + iA + 8)*CCH + h*DKK + d) =
                make_float2(oc[nf][2]*inv8, oc[nf][3]*inv8);
        }
    }
}

// ---------------- out0 = BN1(h1=agg) + BN2(h2) ----------------
__global__ void bn_combine_kernel(const float* __restrict__ ga1, const float* __restrict__ be1,
                                  const float* __restrict__ ga2, const float* __restrict__ be2) {
    int idx = blockIdx.x * blockDim.x + threadIdx.x;
    if (idx >= BNT*CCH/4) return;
    int c0 = (idx << 2) & (CCH - 1);
    float4 a = ((const float4*)g_agg)[idx];
    float4 bb = ((const float4*)g_h2)[idx];
    float av[4] = {a.x, a.y, a.z, a.w};
    float bv[4] = {bb.x, bb.y, bb.z, bb.w};
    float ov[4];
    const float inv_n = 1.f / (float)BNT;
    #pragma unroll
    for (int j = 0; j < 4; j++) {
        int c = c0 + j;
        float m1 = g_ssum[0][c] * inv_n;
        float v1 = g_ssq[0][c] * inv_n - m1*m1;
        float i1 = rsqrtf(v1 + EPSB);
        float m2 = g_ssum[1][c] * inv_n;
        float v2 = g_ssq[1][c] * inv_n - m2*m2;
        float i2 = rsqrtf(v2 + EPSB);
        ov[j] = (av[j]-m1)*i1*ga1[c] + be1[c] + (bv[j]-m2)*i2*ga2[c] + be2[c];
    }
    ((float4*)g_out0)[idx] = make_float4(ov[0], ov[1], ov[2], ov[3]);
}

// ---------------- final BN3 -> output ----------------
__global__ void bn_final_kernel(const float* __restrict__ ga3, const float* __restrict__ be3,
                                float* __restrict__ out) {
    int idx = blockIdx.x * blockDim.x + threadIdx.x;
    if (idx >= BNT*CCH/4) return;
    int c0 = (idx << 2) & (CCH - 1);
    float4 a = ((const float4*)g_out1)[idx];
    float av[4] = {a.x, a.y, a.z, a.w};
    float ov[4];
    const float inv_n = 1.f / (float)BNT;
    #pragma unroll
    for (int j = 0; j < 4; j++) {
        int c = c0 + j;
        float m3 = g_ssum[2][c] * inv_n;
        float v3 = g_ssq[2][c] * inv_n - m3*m3;
        float i3 = rsqrtf(v3 + EPSB);
        ov[j] = (av[j]-m3)*i3*ga3[c] + be3[c];
    }
    ((float4*)out)[idx] = make_float4(ov[0], ov[1], ov[2], ov[3]);
}

// ---------------- launcher ----------------
extern "C" void kernel_launch(void* const* d_in, const int* in_sizes, int n_in,
                              void* d_out, int out_size) {
    const float* x    = (const float*)d_in[0];
    const int*   eidx = (const int*)d_in[1];
    const float* sph  = (const float*)d_in[2];
    const float* Wr   = (const float*)d_in[3];
    const float* Wn   = (const float*)d_in[4];
    const float* Wq   = (const float*)d_in[5];
    const float* bq   = (const float*)d_in[6];
    const float* Wk   = (const float*)d_in[7];
    const float* bk   = (const float*)d_in[8];
    const float* Wv   = (const float*)d_in[9];
    const float* bv   = (const float*)d_in[10];
    const float* Wo   = (const float*)d_in[11];
    const float* bo   = (const float*)d_in[12];
    const float* W1   = (const float*)d_in[13];
    const float* b1   = (const float*)d_in[14];
    const float* W2   = (const float*)d_in[15];
    const float* b2   = (const float*)d_in[16];
    const float* ga1  = (const float*)d_in[17];
    const float* be1  = (const float*)d_in[18];
    const float* ga2  = (const float*)d_in[19];
    const float* be2  = (const float*)d_in[20];
    const float* ga3  = (const float*)d_in[21];
    const float* be3  = (const float*)d_in[22];
    float* out = (float*)d_out;

    float *p_xWn, *p_agg, *p_q, *p_k, *p_v, *p_o, *p_h2, *p_out0, *p_hid, *p_out1;
    float *p_ssum, *p_ssq;
    cudaGetSymbolAddress((void**)&p_xWn,  g_xWn);
    cudaGetSymbolAddress((void**)&p_agg,  g_agg);
    cudaGetSymbolAddress((void**)&p_q,    g_q);
    cudaGetSymbolAddress((void**)&p_k,    g_k);
    cudaGetSymbolAddress((void**)&p_v,    g_v);
    cudaGetSymbolAddress((void**)&p_o,    g_o);
    cudaGetSymbolAddress((void**)&p_h2,   g_h2);
    cudaGetSymbolAddress((void**)&p_out0, g_out0);
    cudaGetSymbolAddress((void**)&p_hid,  g_hid);
    cudaGetSymbolAddress((void**)&p_out1, g_out1);
    cudaGetSymbolAddress((void**)&p_ssum, g_ssum);
    cudaGetSymbolAddress((void**)&p_ssq,  g_ssq);

    cudaFuncSetAttribute(attn_mma_kernel,
                         cudaFuncAttributeMaxDynamicSharedMemorySize, ATT_SMEM_BYTES);

    const int elem4_blocks = (BNT*CCH/4 + 255) / 256;    // 2048

    zero_stats_kernel<<<1, 256>>>();

    // merged projections: xWn, agg(=x@Wr+x), q, k, v in one launch
    P5 p5;
    p5.B[0] = Wn; p5.B[1] = Wr; p5.B[2] = Wq; p5.B[3] = Wk; p5.B[4] = Wv;
    p5.bias[0] = nullptr; p5.bias[1] = nullptr;
    p5.bias[2] = bq; p5.bias[3] = bk; p5.bias[4] = bv;
    p5.res[0] = nullptr; p5.res[1] = x; p5.res[2] = nullptr;
    p5.res[3] = nullptr; p5.res[4] = nullptr;
    p5.C[0] = p_xWn; p5.C[1] = p_agg; p5.C[2] = p_q; p5.C[3] = p_k; p5.C[4] = p_v;
    proj_gemm_kernel<<<dim3(10, BNT/128), 256>>>(x, p5);

    // edge aggregation on top of x@Wr + x
    scatter_kernel<<<EE*64/256, 256>>>(eidx);

    // branch 2: attention + output projection (+x residual)
    attn_mma_kernel<<<dim3(NNODE/128, HH, BB), 256, ATT_SMEM_BYTES>>>(sph);
    sgemm_kernel<<<dim3(CCH/128, BNT/128), 256>>>(p_o, Wo, bo, x, p_h2, CCH, CCH, 0);

    // fused stats for both branches
    colstats2_kernel<<<BNT/64, 256>>>();

    // combine BN branches
    bn_combine_kernel<<<elem4_blocks, 256>>>(ga1, be1, ga2, be2);

    // MLP
    sgemm_kernel<<<dim3(C2/128, BNT/128), 256>>>(p_out0, W1, b1, nullptr, p_hid, C2, CCH, 1);
    sgemm_kernel<<<dim3(CCH/128, BNT/128), 256>>>(p_hid, W2, b2, p_out0, p_out1, CCH, C2, 0);
    colstats_kernel<<<BNT/64, 256>>>(p_out1, p_ssum + 2*CCH, p_ssq + 2*CCH);

    // final BN
    bn_final_kernel<<<elem4_blocks, 256>>>(ga3, be3, out);
}

// round 7
// speedup vs baseline: 4.0266x; 1.1530x over previous
#include <cuda_runtime.h>
#include <cstdint>

// ---------------- problem constants ----------------
#define BNT   8192      // B*N nodes
#define CCH   256       // channels
#define BB    8
#define NNODE 1024
#define HH    8
#define DKK   32
#define EE    131072
#define C2    512
#define EPSB  1e-5f

// ---------------- device scratch ----------------
__device__ float g_xWn [BNT*CCH];
__device__ float g_q   [BNT*CCH];
__device__ float g_k   [BNT*CCH];
__device__ float g_v   [BNT*CCH];
__device__ float g_agg [BNT*CCH];   // h1 = x@Wr + x + segsum
__device__ float g_o   [BNT*CCH];
__device__ float g_h2  [BNT*CCH];
__device__ float g_out0[BNT*CCH];
__device__ float g_hid [BNT*C2];
__device__ float g_out1[BNT*CCH];
__device__ float g_ssum[3][CCH];
__device__ float g_ssq [3][CCH];

// ---------------- zero stats ----------------
__global__ void zero_stats_kernel() {
    int c = threadIdx.x;
    #pragma unroll
    for (int s = 0; s < 3; s++) { g_ssum[s][c] = 0.f; g_ssq[s][c] = 0.f; }
}

// =======================================================================
// tf32 tensor-core GEMM: 128x128 block, BK=16, 256 threads (8 warps),
// warp tile 64x32 = 4x4 m16n8k8 mma. Double-buffered smem.
// Optional fused column stats (sum, sumsq) via shfl-reduce + atomics.
// =======================================================================
#define TAPAD 20
#define TBPAD 136

__device__ __forceinline__ uint32_t f2tf(float x) {
    uint32_t y;
    asm volatile("cvt.rna.tf32.f32 %0, %1;" : "=r"(y) : "f"(x));
    return y;
}

__device__ __forceinline__ void mma8(float* d, const uint32_t* a, const uint32_t* b) {
    asm volatile(
        "mma.sync.aligned.m16n8k8.row.col.f32.tf32.tf32.f32 "
        "{%0,%1,%2,%3}, {%4,%5,%6,%7}, {%8,%9}, {%0,%1,%2,%3};\n"
        : "+f"(d[0]), "+f"(d[1]), "+f"(d[2]), "+f"(d[3])
        : "r"(a[0]), "r"(a[1]), "r"(a[2]), "r"(a[3]),
          "r"(b[0]), "r"(b[1]));
}

__device__ __forceinline__ void mma_gemm_core(
    const float* __restrict__ A, const float* __restrict__ Bm,
    const float* __restrict__ bias, const float* __restrict__ res,
    float* __restrict__ Cc, int N, int K, int block_row, int block_col, int relu,
    float* __restrict__ ssum, float* __restrict__ ssq,
    uint32_t (*As)[128][TAPAD], uint32_t (*Bs)[16][TBPAD])
{
    const int tid  = threadIdx.x;
    const int lane = tid & 31;
    const int w    = tid >> 5;
    const int wm   = (w >> 2) * 64;
    const int wn   = (w & 3) * 32;
    const int qr   = lane >> 2;
    const int qc   = lane & 3;

    const int aRow = tid >> 1;
    const int aK   = (tid & 1) * 8;
    const int bRow = tid >> 4;
    const int bCol = (tid & 15) * 8;

    const float* Aptr = A + (size_t)(block_row*128) * K;
    const float* Bptr = Bm + block_col*128;

    float acc[4][4][4];
    #pragma unroll
    for (int mi = 0; mi < 4; mi++)
        #pragma unroll
        for (int ni = 0; ni < 4; ni++)
            #pragma unroll
            for (int r = 0; r < 4; r++) acc[mi][ni][r] = 0.f;

    const int nstages = K >> 4;
    float4 ra0, ra1, rb0, rb1;

    ra0 = *(const float4*)(Aptr + (size_t)aRow*K + aK);
    ra1 = *(const float4*)(Aptr + (size_t)aRow*K + aK + 4);
    rb0 = *(const float4*)(Bptr + (size_t)bRow*N + bCol);
    rb1 = *(const float4*)(Bptr + (size_t)bRow*N + bCol + 4);
    {
        uint4 u;
        u.x = f2tf(ra0.x); u.y = f2tf(ra0.y); u.z = f2tf(ra0.z); u.w = f2tf(ra0.w);
        *(uint4*)&As[0][aRow][aK] = u;
        u.x = f2tf(ra1.x); u.y = f2tf(ra1.y); u.z = f2tf(ra1.z); u.w = f2tf(ra1.w);
        *(uint4*)&As[0][aRow][aK + 4] = u;
        u.x = f2tf(rb0.x); u.y = f2tf(rb0.y); u.z = f2tf(rb0.z); u.w = f2tf(rb0.w);
        *(uint4*)&Bs[0][bRow][bCol] = u;
        u.x = f2tf(rb1.x); u.y = f2tf(rb1.y); u.z = f2tf(rb1.z); u.w = f2tf(rb1.w);
        *(uint4*)&Bs[0][bRow][bCol + 4] = u;
    }
    __syncthreads();

    for (int s = 0; s < nstages; s++) {
        const int buf = s & 1;
        const bool more = (s + 1 < nstages);
        if (more) {
            int k0 = (s + 1) << 4;
            ra0 = *(const float4*)(Aptr + (size_t)aRow*K + k0 + aK);
            ra1 = *(const float4*)(Aptr + (size_t)aRow*K + k0 + aK + 4);
            rb0 = *(const float4*)(Bptr + (size_t)(k0 + bRow)*N + bCol);
            rb1 = *(const float4*)(Bptr + (size_t)(k0 + bRow)*N + bCol + 4);
        }

        #pragma unroll
        for (int ks = 0; ks < 2; ks++) {
            const int kk = ks * 8;
            uint32_t af[4][4], bf[4][2];
            #pragma unroll
            for (int mi = 0; mi < 4; mi++) {
                int m = wm + mi*16 + qr;
                af[mi][0] = As[buf][m    ][kk + qc];
                af[mi][1] = As[buf][m + 8][kk + qc];
                af[mi][2] = As[buf][m    ][kk + qc + 4];
                af[mi][3] = As[buf][m + 8][kk + qc + 4];
            }
            #pragma unroll
            for (int ni = 0; ni < 4; ni++) {
                int n = wn + ni*8 + qr;
                bf[ni][0] = Bs[buf][kk + qc    ][n];
                bf[ni][1] = Bs[buf][kk + qc + 4][n];
            }
            #pragma unroll
            for (int mi = 0; mi < 4; mi++)
                #pragma unroll
                for (int ni = 0; ni < 4; ni++)
                    mma8(acc[mi][ni], af[mi], bf[ni]);
        }

        if (more) {
            const int nb = buf ^ 1;
            uint4 u;
            u.x = f2tf(ra0.x); u.y = f2tf(ra0.y); u.z = f2tf(ra0.z); u.w = f2tf(ra0.w);
            *(uint4*)&As[nb][aRow][aK] = u;
            u.x = f2tf(ra1.x); u.y = f2tf(ra1.y); u.z = f2tf(ra1.z); u.w = f2tf(ra1.w);
            *(uint4*)&As[nb][aRow][aK + 4] = u;
            u.x = f2tf(rb0.x); u.y = f2tf(rb0.y); u.z = f2tf(rb0.z); u.w = f2tf(rb0.w);
            *(uint4*)&Bs[nb][bRow][bCol] = u;
            u.x = f2tf(rb1.x); u.y = f2tf(rb1.y); u.z = f2tf(rb1.z); u.w = f2tf(rb1.w);
            *(uint4*)&Bs[nb][bRow][bCol + 4] = u;
        }
        __syncthreads();
    }

    const int row0 = block_row*128 + wm;
    const int col0 = block_col*128 + wn;

    float cs[4][2], cq[4][2];
    #pragma unroll
    for (int ni = 0; ni < 4; ni++) {
        cs[ni][0] = cs[ni][1] = 0.f;
        cq[ni][0] = cq[ni][1] = 0.f;
    }

    #pragma unroll
    for (int mi = 0; mi < 4; mi++) {
        #pragma unroll
        for (int half = 0; half < 2; half++) {
            const int r = row0 + mi*16 + qr + half*8;
            #pragma unroll
            for (int ni = 0; ni < 4; ni++) {
                const int c = col0 + ni*8 + 2*qc;
                float v0 = acc[mi][ni][half*2 + 0];
                float v1 = acc[mi][ni][half*2 + 1];
                if (bias) { v0 += bias[c]; v1 += bias[c+1]; }
                if (res) {
                    float2 rv = *(const float2*)(res + (size_t)r*N + c);
                    v0 += rv.x; v1 += rv.y;
                }
                if (relu) { v0 = fmaxf(v0, 0.f); v1 = fmaxf(v1, 0.f); }
                if (ssum) {
                    cs[ni][0] += v0; cs[ni][1] += v1;
                    cq[ni][0] += v0*v0; cq[ni][1] += v1*v1;
                }
                *(float2*)(Cc + (size_t)r*N + c) = make_float2(v0, v1);
            }
        }
    }

    if (ssum) {
        #pragma unroll
        for (int ni = 0; ni < 4; ni++) {
            #pragma unroll
            for (int e = 0; e < 2; e++) {
                float s = cs[ni][e], q = cq[ni][e];
                #pragma unroll
                for (int off = 4; off < 32; off <<= 1) {
                    s += __shfl_xor_sync(0xffffffffu, s, off);
                    q += __shfl_xor_sync(0xffffffffu, q, off);
                }
                if (qr == 0) {
                    int c = col0 + ni*8 + 2*qc + e;
                    atomicAdd(&ssum[c], s);
                    atomicAdd(&ssq[c], q);
                }
            }
        }
    }
}

// ---------------- generic GEMM (Wo, MLP) ----------------
__global__ __launch_bounds__(256, 2)
void sgemm_kernel(const float* __restrict__ A, const float* __restrict__ Bm,
                  const float* __restrict__ bias, const float* __restrict__ res,
                  float* __restrict__ Cc, int N, int K, int relu,
                  float* ssum, float* ssq)
{
    __shared__ uint32_t As[2][128][TAPAD];
    __shared__ uint32_t Bs[2][16][TBPAD];
    mma_gemm_core(A, Bm, bias, res, Cc, N, K, blockIdx.y, blockIdx.x, relu,
                  ssum, ssq, As, Bs);
}

// ---------------- merged 5-way projection GEMM ----------------
struct P5 {
    const float* B[5];
    const float* bias[5];
    const float* res[5];
    float*       C[5];
};

__global__ __launch_bounds__(256, 2)
void proj_gemm_kernel(const float* __restrict__ A, P5 p)
{
    __shared__ uint32_t As[2][128][TAPAD];
    __shared__ uint32_t Bs[2][16][TBPAD];
    const int bw = blockIdx.x >> 1;
    const int bc = blockIdx.x & 1;
    mma_gemm_core(A, p.B[bw], p.bias[bw], p.res[bw], p.C[bw],
                  CCH, CCH, blockIdx.y, bc, 0, nullptr, nullptr, As, Bs);
}

// ---------------- edge scatter: agg[dst] += xWn[src] (vector red) ------
__global__ void scatter_kernel(const int* __restrict__ ei) {
    int t = blockIdx.x * blockDim.x + threadIdx.x;
    if (t >= EE*64) return;
    int e = t >> 6;
    int j = (t & 63) * 4;
    int src = ei[e];
    int dst = ei[EE + e];
    float4 mv = *(const float4*)(g_xWn + (size_t)src*CCH + j);
    float* p = g_agg + (size_t)dst*CCH + j;
    asm volatile("red.global.add.v4.f32 [%0], {%1,%2,%3,%4};"
                 :: "l"(p), "f"(mv.x), "f"(mv.y), "f"(mv.z), "f"(mv.w)
                 : "memory");
}

// ---------------- per-column stats (h1 = agg) -> slot 0 ----------------
__global__ void colstats_kernel(const float* __restrict__ X,
                                float* __restrict__ ssum, float* __restrict__ ssq) {
    int c = threadIdx.x;
    size_t r0 = (size_t)blockIdx.x * 64;
    float s = 0.f, q = 0.f;
    #pragma unroll 4
    for (int rr = 0; rr < 64; rr++) {
        float v = X[(r0 + rr)*CCH + c];
        s += v; q += v * v;
    }
    atomicAdd(&ssum[c], s);
    atomicAdd(&ssq[c], q);
}

// =======================================================================
// tf32 mma attention, fragment-packed smem layouts.
// S^T = K Q^T per 64-key chunk; P transposed in smem feeds PV directly.
// Non-online softmax (bounded scores); rowsum divide at the end.
// grid: (N/128, H, B), 256 threads, dynamic smem.
// =======================================================================
// QP: Q fragments [t=16][ks=4][lane=32][2]   stride 64/row  (LDS.64, cf-free)
// KP: K fragments [mt=4][ks=4][lane=32][4]   stride 132/row (LDS.128, cf-free)
// VP: V fragments [nf=4][ks=8][lane=32][2]   stride 66/row  (LDS.64, cf-free)
// Pt: transposed P [64][PTS]
#define PTS 136
#define QP_WORDS (16*4*64)     // 4096
#define KP_WORDS (16*132)      // 2112
#define VP_WORDS (32*66)       // 2112
#define PT_WORDS (64*PTS)      // 8704
#define ATT_SMEM_WORDS (QP_WORDS + KP_WORDS + VP_WORDS + PT_WORDS + 128)
#define ATT_SMEM_BYTES (ATT_SMEM_WORDS*4)

__global__ __launch_bounds__(256, 2)
void attn_mma_kernel(const float* __restrict__ sph) {
    extern __shared__ uint32_t smem[];
    uint32_t* QP = smem;
    uint32_t* KP = QP + QP_WORDS;
    uint32_t* VP = KP + KP_WORDS;
    uint32_t* Pt = VP + VP_WORDS;
    float*  lsum = (float*)(Pt + PT_WORDS);

    const int i0   = blockIdx.x * 128;
    const int h    = blockIdx.y;
    const int b    = blockIdx.z;
    const int tid  = threadIdx.x;
    const int lane = tid & 31;
    const int w    = tid >> 5;
    const int qr   = lane >> 2;
    const int qc   = lane & 3;

    const size_t base = (size_t)b*NNODE*CCH + h*DKK;
    const float rscale = 0.17677669529663688f;  // 1/sqrt(32)

    // ---- pack Q fragments (once per block) ----
    for (int idx = tid; idx < 128*8; idx += 256) {
        int i = idx >> 3, c4 = (idx & 7) * 4;
        float4 qv = *(const float4*)(g_q + base + (size_t)(i0+i)*CCH + c4);
        const int t = i >> 3, qri = i & 7;
        float vals[4] = {qv.x, qv.y, qv.z, qv.w};
        #pragma unroll
        for (int m = 0; m < 4; m++) {
            int c = c4 + m;
            int ks = c >> 3, qci = c & 3, chalf = (c >> 2) & 1;
            QP[(t*4 + ks)*64 + (qri*4 + qci)*2 + chalf] = f2tf(vals[m]);
        }
    }
    if (tid < 128) lsum[tid] = 0.f;

    float oc[4][4];
    float rs[8][2];
    #pragma unroll
    for (int a = 0; a < 4; a++)
        #pragma unroll
        for (int r = 0; r < 4; r++) oc[a][r] = 0.f;
    #pragma unroll
    for (int a = 0; a < 8; a++) { rs[a][0] = 0.f; rs[a][1] = 0.f; }

    const int m0k  = (w & 3) * 16;    // QK: key m-tile base
    const int mtk  = (w & 3);         // QK: key m-tile index
    const int nbq  = (w >> 2) * 64;   // QK: q n-range base
    const int tbq  = (w >> 2) * 8;    // QK: q n-tile index base
    const int m0o  = w * 16;          // PV: q-row m-tile

    const float* sphb = sph + ((size_t)b*NNODE + i0)*NNODE;

    for (int jt = 0; jt < NNODE; jt += 64) {
        __syncthreads();   // prev iter's consumers done
        // ---- pack K and V fragments for this chunk ----
        for (int idx = tid; idx < 64*8; idx += 256) {
            int j = idx >> 3, c4 = (idx & 7) * 4;
            float4 kv = *(const float4*)(g_k + base + (size_t)(jt+j)*CCH + c4);
            float4 vv = *(const float4*)(g_v + base + (size_t)(jt+j)*CCH + c4);
            float kvals[4] = {kv.x, kv.y, kv.z, kv.w};
            float vvals[4] = {vv.x, vv.y, vv.z, vv.w};
            // K: j = key row (m), c = k-dim
            const int mt = j >> 4, qrj = j & 7, half = (j >> 3) & 1;
            #pragma unroll
            for (int m = 0; m < 4; m++) {
                int c = c4 + m;
                int ks = c >> 3, qci = c & 3, chalf = (c >> 2) & 1;
                KP[(mt*4 + ks)*132 + (qrj*4 + qci)*4 + half + 2*chalf] = f2tf(kvals[m]);
            }
            // V: j = key (k-dim of PV), c = d (n-dim)
            const int ksv = j >> 3, qcv = j & 3, chv = (j >> 2) & 1;
            #pragma unroll
            for (int m = 0; m < 4; m++) {
                int c = c4 + m;
                int nf = c >> 3, qrv = c & 7;
                VP[(nf*8 + ksv)*66 + (qrv*4 + qcv)*2 + chv] = f2tf(vvals[m]);
            }
        }
        __syncthreads();

        // ---- S^T = K Q^T ----
        float sc[8][4];
        #pragma unroll
        for (int ni = 0; ni < 8; ni++)
            #pragma unroll
            for (int r = 0; r < 4; r++) sc[ni][r] = 0.f;

        #pragma unroll
        for (int ks = 0; ks < 4; ks++) {
            uint4 afv = *(const uint4*)&KP[(mtk*4 + ks)*132 + lane*4];
            uint32_t af[4] = {afv.x, afv.y, afv.z, afv.w};
            #pragma unroll
            for (int ni = 0; ni < 8; ni++) {
                uint2 bfv = *(const uint2*)&QP[((tbq + ni)*4 + ks)*64 + lane*2];
                uint32_t bf[2] = {bfv.x, bfv.y};
                mma8(sc[ni], af, bf);
            }
        }

        // ---- exp(sc * rscale * sph) -> Pt, rowsums ----
        #pragma unroll
        for (int ni = 0; ni < 8; ni++) {
            const int iA = nbq + ni*8 + 2*qc;
            const int jA = m0k + qr;
            const float* s0p = sphb + (size_t)iA*NNODE + jt + jA;
            float sp00 = s0p[0];
            float sp08 = s0p[8];
            float sp10 = s0p[NNODE];
            float sp18 = s0p[NNODE + 8];
            float p0 = __expf(sc[ni][0] * rscale * sp00);
            float p1 = __expf(sc[ni][1] * rscale * sp10);
            float p2 = __expf(sc[ni][2] * rscale * sp08);
            float p3 = __expf(sc[ni][3] * rscale * sp18);
            rs[ni][0] += p0 + p2;
            rs[ni][1] += p1 + p3;
            uint2 w0; w0.x = f2tf(p0); w0.y = f2tf(p1);
            uint2 w1; w1.x = f2tf(p2); w1.y = f2tf(p3);
            *(uint2*)&Pt[(size_t)jA*PTS + iA] = w0;
            *(uint2*)&Pt[(size_t)(jA+8)*PTS + iA] = w1;
        }
        __syncthreads();   // Pt ready

        // ---- O += P V ----
        #pragma unroll
        for (int ks = 0; ks < 8; ks++) {
            const int kk = ks * 8;
            uint32_t af[4];
            af[0] = Pt[(kk+qc  )*PTS + m0o+qr];
            af[1] = Pt[(kk+qc  )*PTS + m0o+qr+8];
            af[2] = Pt[(kk+qc+4)*PTS + m0o+qr];
            af[3] = Pt[(kk+qc+4)*PTS + m0o+qr+8];
            #pragma unroll
            for (int nf = 0; nf < 4; nf++) {
                uint2 bfv = *(const uint2*)&VP[(nf*8 + ks)*66 + lane*2];
                uint32_t bf[2] = {bfv.x, bfv.y};
                mma8(oc[nf], af, bf);
            }
        }
    }

    // ---- rowsum reduce + accumulate across warps ----
    #pragma unroll
    for (int ni = 0; ni < 8; ni++) {
        #pragma unroll
        for (int e = 0; e < 2; e++) {
            float v = rs[ni][e];
            v += __shfl_xor_sync(0xffffffffu, v, 4);
            v += __shfl_xor_sync(0xffffffffu, v, 8);
            v += __shfl_xor_sync(0xffffffffu, v, 16);
            rs[ni][e] = v;
        }
    }
    if (qr == 0) {
        #pragma unroll
        for (int ni = 0; ni < 8; ni++) {
            atomicAdd(&lsum[nbq + ni*8 + 2*qc    ], rs[ni][0]);
            atomicAdd(&lsum[nbq + ni*8 + 2*qc + 1], rs[ni][1]);
        }
    }
    __syncthreads();

    // ---- normalize + write O ----
    {
        const int iA = m0o + qr;
        const float inv0 = 1.f / lsum[iA];
        const float inv8 = 1.f / lsum[iA + 8];
        #pragma unroll
        for (int nf = 0; nf < 4; nf++) {
            const int d = nf*8 + 2*qc;
            *(float2*)(g_o + ((size_t)b*NNODE + i0 + iA)*CCH + h*DKK + d) =
                make_float2(oc[nf][0]*inv0, oc[nf][1]*inv0);
            *(float2*)(g_o + ((size_t)b*NNODE + i0 + iA + 8)*CCH + h*DKK + d) =
                make_float2(oc[nf][2]*inv8, oc[nf][3]*inv8);
        }
    }
}

// ---------------- out0 = BN1(h1=agg) + BN2(h2) ----------------
__global__ void bn_combine_kernel(const float* __restrict__ ga1, const float* __restrict__ be1,
                                  const float* __restrict__ ga2, const float* __restrict__ be2) {
    int idx = blockIdx.x * blockDim.x + threadIdx.x;
    if (idx >= BNT*CCH/4) return;
    int c0 = (idx << 2) & (CCH - 1);
    float4 a = ((const float4*)g_agg)[idx];
    float4 bb = ((const float4*)g_h2)[idx];
    float av[4] = {a.x, a.y, a.z, a.w};
    float bv[4] = {bb.x, bb.y, bb.z, bb.w};
    float ov[4];
    const float inv_n = 1.f / (float)BNT;
    #pragma unroll
    for (int j = 0; j < 4; j++) {
        int c = c0 + j;
        float m1 = g_ssum[0][c] * inv_n;
        float v1 = g_ssq[0][c] * inv_n - m1*m1;
        float i1 = rsqrtf(v1 + EPSB);
        float m2 = g_ssum[1][c] * inv_n;
        float v2 = g_ssq[1][c] * inv_n - m2*m2;
        float i2 = rsqrtf(v2 + EPSB);
        ov[j] = (av[j]-m1)*i1*ga1[c] + be1[c] + (bv[j]-m2)*i2*ga2[c] + be2[c];
    }
    ((float4*)g_out0)[idx] = make_float4(ov[0], ov[1], ov[2], ov[3]);
}

// ---------------- final BN3 -> output ----------------
__global__ void bn_final_kernel(const float* __restrict__ ga3, const float* __restrict__ be3,
                                float* __restrict__ out) {
    int idx = blockIdx.x * blockDim.x + threadIdx.x;
    if (idx >= BNT*CCH/4) return;
    int c0 = (idx << 2) & (CCH - 1);
    float4 a = ((const float4*)g_out1)[idx];
    float av[4] = {a.x, a.y, a.z, a.w};
    float ov[4];
    const float inv_n = 1.f / (float)BNT;
    #pragma unroll
    for (int j = 0; j < 4; j++) {
        int c = c0 + j;
        float m3 = g_ssum[2][c] * inv_n;
        float v3 = g_ssq[2][c] * inv_n - m3*m3;
        float i3 = rsqrtf(v3 + EPSB);
        ov[j] = (av[j]-m3)*i3*ga3[c] + be3[c];
    }
    ((float4*)out)[idx] = make_float4(ov[0], ov[1], ov[2], ov[3]);
}

// ---------------- launcher ----------------
extern "C" void kernel_launch(void* const* d_in, const int* in_sizes, int n_in,
                              void* d_out, int out_size) {
    const float* x    = (const float*)d_in[0];
    const int*   eidx = (const int*)d_in[1];
    const float* sph  = (const float*)d_in[2];
    const float* Wr   = (const float*)d_in[3];
    const float* Wn   = (const float*)d_in[4];
    const float* Wq   = (const float*)d_in[5];
    const float* bq   = (const float*)d_in[6];
    const float* Wk   = (const float*)d_in[7];
    const float* bk   = (const float*)d_in[8];
    const float* Wv   = (const float*)d_in[9];
    const float* bv   = (const float*)d_in[10];
    const float* Wo   = (const float*)d_in[11];
    const float* bo   = (const float*)d_in[12];
    const float* W1   = (const float*)d_in[13];
    const float* b1   = (const float*)d_in[14];
    const float* W2   = (const float*)d_in[15];
    const float* b2   = (const float*)d_in[16];
    const float* ga1  = (const float*)d_in[17];
    const float* be1  = (const float*)d_in[18];
    const float* ga2  = (const float*)d_in[19];
    const float* be2  = (const float*)d_in[20];
    const float* ga3  = (const float*)d_in[21];
    const float* be3  = (const float*)d_in[22];
    float* out = (float*)d_out;

    float *p_xWn, *p_agg, *p_q, *p_k, *p_v, *p_o, *p_h2, *p_out0, *p_hid, *p_out1;
    float *p_ssum, *p_ssq;
    cudaGetSymbolAddress((void**)&p_xWn,  g_xWn);
    cudaGetSymbolAddress((void**)&p_agg,  g_agg);
    cudaGetSymbolAddress((void**)&p_q,    g_q);
    cudaGetSymbolAddress((void**)&p_k,    g_k);
    cudaGetSymbolAddress((void**)&p_v,    g_v);
    cudaGetSymbolAddress((void**)&p_o,    g_o);
    cudaGetSymbolAddress((void**)&p_h2,   g_h2);
    cudaGetSymbolAddress((void**)&p_out0, g_out0);
    cudaGetSymbolAddress((void**)&p_hid,  g_hid);
    cudaGetSymbolAddress((void**)&p_out1, g_out1);
    cudaGetSymbolAddress((void**)&p_ssum, g_ssum);
    cudaGetSymbolAddress((void**)&p_ssq,  g_ssq);

    cudaFuncSetAttribute(attn_mma_kernel,
                         cudaFuncAttributeMaxDynamicSharedMemorySize, ATT_SMEM_BYTES);

    const int elem4_blocks = (BNT*CCH/4 + 255) / 256;    // 2048

    zero_stats_kernel<<<1, 256>>>();

    // merged projections: xWn, agg(=x@Wr+x), q, k, v in one launch
    P5 p5;
    p5.B[0] = Wn; p5.B[1] = Wr; p5.B[2] = Wq; p5.B[3] = Wk; p5.B[4] = Wv;
    p5.bias[0] = nullptr; p5.bias[1] = nullptr;
    p5.bias[2] = bq; p5.bias[3] = bk; p5.bias[4] = bv;
    p5.res[0] = nullptr; p5.res[1] = x; p5.res[2] = nullptr;
    p5.res[3] = nullptr; p5.res[4] = nullptr;
    p5.C[0] = p_xWn; p5.C[1] = p_agg; p5.C[2] = p_q; p5.C[3] = p_k; p5.C[4] = p_v;
    proj_gemm_kernel<<<dim3(10, BNT/128), 256>>>(x, p5);

    // edge aggregation on top of x@Wr + x
    scatter_kernel<<<EE*64/256, 256>>>(eidx);

    // h1 stats (slot 0)
    colstats_kernel<<<BNT/64, 256>>>(p_agg, p_ssum + 0*CCH, p_ssq + 0*CCH);

    // branch 2: attention + output projection (+x residual, fused h2 stats slot 1)
    attn_mma_kernel<<<dim3(NNODE/128, HH, BB), 256, ATT_SMEM_BYTES>>>(sph);
    sgemm_kernel<<<dim3(CCH/128, BNT/128), 256>>>(p_o, Wo, bo, x, p_h2, CCH, CCH, 0,
                                                  p_ssum + 1*CCH, p_ssq + 1*CCH);

    // combine BN branches
    bn_combine_kernel<<<elem4_blocks, 256>>>(ga1, be1, ga2, be2);

    // MLP (W2 gemm fuses out1 stats slot 2)
    sgemm_kernel<<<dim3(C2/128, BNT/128), 256>>>(p_out0, W1, b1, nullptr, p_hid, C2, CCH, 1,
                                                 nullptr, nullptr);
    sgemm_kernel<<<dim3(CCH/128, BNT/128), 256>>>(p_hid, W2, b2, p_out0, p_out1, CCH, C2, 0,
                                                  p_ssum + 2*CCH, p_ssq + 2*CCH);

    // final BN
    bn_final_kernel<<<elem4_blocks, 256>>>(ga3, be3, out);
}